// round 15
// baseline (speedup 1.0000x reference)
#include <cuda_runtime.h>
#include <cuda_bf16.h>
#include <cstdint>
#include <math.h>

// Problem constants
#define BB 8
#define SS 512
#define HH 768
#define NHH 12
#define DHH 64
#define LL 12
#define VV 21128
#define FFF 3072
#define PLEN 128
#define NTOK (BB*SS)
#define NVALID_PER_B (SS-PLEN)
#define NVALID (BB*NVALID_PER_B)
#define QKVW (3*HH)            // 2304

// ---------------- scratch (device globals; no allocations allowed) ----------
__device__ float g_h[NTOK*HH];                       // fp32 residual stream
__device__ __nv_bfloat16 g_hhi[NTOK*HH];
__device__ __nv_bfloat16 g_hlo[NTOK*HH];
__device__ __nv_bfloat16 g_qkvh[(size_t)NTOK*QKVW];
__device__ __nv_bfloat16 g_qkvl[(size_t)NTOK*QKVW];
__device__ __nv_bfloat16 g_ctxh[NTOK*HH];
__device__ __nv_bfloat16 g_ctxl[NTOK*HH];
__device__ float g_tmp[NTOK*HH];
__device__ __nv_bfloat16 g_ffnh[(size_t)NTOK*FFF];
__device__ __nv_bfloat16 g_ffnl[(size_t)NTOK*FFF];
__device__ float g_scores[(size_t)BB*NHH*SS*SS];
__device__ __nv_bfloat16 g_schi[(size_t)BB*NHH*SS*SS];
__device__ __nv_bfloat16 g_sclo[(size_t)BB*NHH*SS*SS];
__device__ float g_logits[(size_t)NVALID*VV];
// split weights
__device__ __nv_bfloat16 g_wqkvh[(size_t)LL*HH*QKVW];
__device__ __nv_bfloat16 g_wqkvl[(size_t)LL*HH*QKVW];
__device__ float g_bqkv[(size_t)LL*QKVW];
__device__ __nv_bfloat16 g_woh[(size_t)LL*HH*HH];
__device__ __nv_bfloat16 g_wol[(size_t)LL*HH*HH];
__device__ __nv_bfloat16 g_w1h[(size_t)LL*HH*FFF];
__device__ __nv_bfloat16 g_w1l[(size_t)LL*HH*FFF];
__device__ __nv_bfloat16 g_w2h[(size_t)LL*FFF*HH];
__device__ __nv_bfloat16 g_w2l[(size_t)LL*FFF*HH];
__device__ __nv_bfloat16 g_wch[(size_t)HH*VV];
__device__ __nv_bfloat16 g_wcl[(size_t)HH*VV];
__device__ float g_loss_sum;

// ---------------- helpers ----------------------------------------------------
__device__ __forceinline__ float warpSum(float v){
  #pragma unroll
  for (int o=16;o;o>>=1) v += __shfl_xor_sync(0xffffffffu, v, o);
  return v;
}
__device__ __forceinline__ float warpMax(float v){
  #pragma unroll
  for (int o=16;o;o>>=1) v = fmaxf(v, __shfl_xor_sync(0xffffffffu, v, o));
  return v;
}
template<int NW>
__device__ __forceinline__ float blockSum(float v){
  __shared__ float sh[NW];
  __syncthreads();
  v = warpSum(v);
  if ((threadIdx.x & 31)==0) sh[threadIdx.x>>5] = v;
  __syncthreads();
  float r = 0.f;
  #pragma unroll
  for (int i=0;i<NW;i++) r += sh[i];
  return r;
}
template<int NW>
__device__ __forceinline__ float blockMax(float v){
  __shared__ float sh[NW];
  __syncthreads();
  v = warpMax(v);
  if ((threadIdx.x & 31)==0) sh[threadIdx.x>>5] = v;
  __syncthreads();
  float r = -3.4e38f;
  #pragma unroll
  for (int i=0;i<NW;i++) r = fmaxf(r, sh[i]);
  return r;
}
__device__ __forceinline__ float gelu_exact(float x){
  return 0.5f * x * (1.0f + erff(x * 0.70710678118654752f));
}
__device__ __forceinline__ uint32_t smem_u32(const void* p){
  uint32_t a;
  asm("{ .reg .u64 t; cvta.to.shared.u64 t, %1; cvt.u32.u64 %0, t; }" : "=r"(a) : "l"(p));
  return a;
}
__device__ __forceinline__ void cp16(uint32_t dst, const void* src){
  asm volatile("cp.async.ca.shared.global [%0], [%1], 16;" :: "r"(dst), "l"(src));
}
__device__ __forceinline__ void cp16p(uint32_t dst, const void* src, bool valid){
  int sz = valid ? 16 : 0;
  asm volatile("cp.async.ca.shared.global [%0], [%1], 16, %2;"
               :: "r"(dst), "l"(src), "r"(sz));
}
__device__ __forceinline__ void cp_commit(){
  asm volatile("cp.async.commit_group;" ::: "memory");
}
template<int N>
__device__ __forceinline__ void cp_wait(){
  asm volatile("cp.async.wait_group %0;" :: "n"(N) : "memory");
}

// split a pair of fp32 into packed bf16 hi and lo (x0 -> low half)
__device__ __forceinline__ void split_bf16_pair(float x0, float x1,
                                                uint32_t& hi, uint32_t& lo){
  uint32_t h;
  asm("cvt.rn.bf16x2.f32 %0, %1, %2;" : "=r"(h) : "f"(x1), "f"(x0));
  float h0 = __uint_as_float(h << 16);
  float h1 = __uint_as_float(h & 0xffff0000u);
  float l0 = x0 - h0;
  float l1 = x1 - h1;
  asm("cvt.rn.bf16x2.f32 %0, %1, %2;" : "=r"(lo) : "f"(l1), "f"(l0));
  hi = h;
}
__device__ __forceinline__ void split_bf16_scalar(float x, __nv_bfloat16& h, __nv_bfloat16& l){
  h = __float2bfloat16(x);
  l = __float2bfloat16(x - __bfloat162float(h));
}

__device__ __forceinline__ void mma_bf16(float* d, const uint32_t* a, const uint32_t* b){
  asm volatile(
    "mma.sync.aligned.m16n8k16.row.col.f32.bf16.bf16.f32 "
    "{%0,%1,%2,%3}, {%4,%5,%6,%7}, {%8,%9}, {%0,%1,%2,%3};\n"
    : "+f"(d[0]), "+f"(d[1]), "+f"(d[2]), "+f"(d[3])
    : "r"(a[0]), "r"(a[1]), "r"(a[2]), "r"(a[3]), "r"(b[0]), "r"(b[1]));
}
__device__ __forceinline__ void ldsm_x4(uint32_t* r, uint32_t addr){
  asm volatile("ldmatrix.sync.aligned.m8n8.x4.shared.b16 {%0,%1,%2,%3}, [%4];"
    : "=r"(r[0]), "=r"(r[1]), "=r"(r[2]), "=r"(r[3]) : "r"(addr));
}
__device__ __forceinline__ void ldsm_x4_t(uint32_t* r, uint32_t addr){
  asm volatile("ldmatrix.sync.aligned.m8n8.x4.trans.shared.b16 {%0,%1,%2,%3}, [%4];"
    : "=r"(r[0]), "=r"(r[1]), "=r"(r[2]), "=r"(r[3]) : "r"(addr));
}

// ---------------- 3xBF16 GEMM, pre-split bf16, cp.async 3-stage, BK=32 -------
// C = A @ op(B) (+bias)(+GELU). A,B given as bf16 hi/lo pairs in gmem.
// TRANSB: B is [N,K] (NT). OUT: 0 -> fp32 C; 1 -> bf16 hi/lo C.
// MASK: 0 none; 1 scores (skip CTA if n0>=m0+128); 2 AV (truncate K at m0+128).
// BN=64, warp tile 32x32, ONE __syncthreads per 32-K chunk.
// MMA issued in 3 independent passes (hh, lh, hl) to break accumulator RAW chains.
template<int BN, bool TRANSB, int ACT, int OUT, int MASK>
__global__ __launch_bounds__(256,2) void gemm_mma(
    const __nv_bfloat16* __restrict__ Agh, const __nv_bfloat16* __restrict__ Agl,
    const __nv_bfloat16* __restrict__ Bgh, const __nv_bfloat16* __restrict__ Bgl,
    const float* __restrict__ bias,
    float* __restrict__ Cf, __nv_bfloat16* __restrict__ Ch, __nv_bfloat16* __restrict__ Cl,
    int M, int N, int K, int lda, int ldb, int ldc,
    int batchInner,
    long long sA1, long long sA2, long long sB1, long long sB2,
    long long sC1, long long sC2)
{
  constexpr int BM = 128;
  constexpr int BK = 32;
  constexpr int STAGES = 3;
  constexpr int WM = 32, WN = 32;
  constexpr int MF = 2, NF = 4;
  constexpr int WARPS_N = BN/32;         // 2

  constexpr int AP = 40;                            // 80B rows: aligned + conflict-free
  constexpr int BROWS = TRANSB ? BN : BK;
  constexpr int BP = TRANSB ? 40 : (BN + 8);        // 80B / 144B rows
  constexpr int A_EL = BM*AP;
  constexpr int B_EL = BROWS*BP;
  constexpr int STAGE_EL = 2*A_EL + 2*B_EL;

  const int m0 = blockIdx.y * BM;
  const int n0 = blockIdx.x * BN;
  if (MASK == 1 && n0 >= m0 + BM) return;

  extern __shared__ __nv_bfloat16 sm[];

  const int tid  = threadIdx.x;
  const int wid  = tid >> 5;
  const int lane = tid & 31;
  const int grp  = lane >> 2;
  const int tig  = lane & 3;

  const int z  = blockIdx.z;
  const int zo = z / batchInner;
  const int zi = z - zo * batchInner;
  const __nv_bfloat16* Ah_g = Agh + zo*sA1 + zi*sA2;
  const __nv_bfloat16* Al_g = Agl + zo*sA1 + zi*sA2;
  const __nv_bfloat16* Bh_g = Bgh + zo*sB1 + zi*sB2;
  const __nv_bfloat16* Bl_g = Bgl + zo*sB1 + zi*sB2;

  const int wm = (wid / WARPS_N) * WM;
  const int wn = (wid % WARPS_N) * WN;

  float acc[MF][NF][4];
  #pragma unroll
  for (int i=0;i<MF;i++)
    #pragma unroll
    for (int j=0;j<NF;j++)
      #pragma unroll
      for (int r=0;r<4;r++) acc[i][j][r] = 0.f;

  int Keff = K;
  if (MASK == 2) Keff = (m0 + BM < K) ? (m0 + BM) : K;
  const int nch = Keff / BK;

  // loader index precompute (BK=32)
  const int aRow = tid >> 2;             // 0..63 (i=0), +64 (i=1)
  const int aQ   = tid & 3;              // 16B quarter within 64B row
  const int bnRow = tid >> 2;            // NT: 0..63
  const int bnQ   = tid & 3;
  const int bkK  = tid >> 3;             // NN: 0..31
  const int bkNg = tid & 7;              // NN: n group (8 bf16)

  auto loadStage = [&](int c, int s){
    const int k0 = c * BK;
    __nv_bfloat16* Ahs = sm + s*STAGE_EL;
    __nv_bfloat16* Als = Ahs + A_EL;
    __nv_bfloat16* Bhs = Als + A_EL;
    __nv_bfloat16* Bls = Bhs + B_EL;
    #pragma unroll
    for (int i=0;i<2;i++){
      int row = aRow + i*64;
      size_t off = (size_t)(m0+row)*lda + k0 + aQ*8;
      cp16(smem_u32(Ahs + row*AP + aQ*8), Ah_g + off);
      cp16(smem_u32(Als + row*AP + aQ*8), Al_g + off);
    }
    if (TRANSB){
      size_t off = (size_t)(n0+bnRow)*ldb + k0 + bnQ*8;
      cp16(smem_u32(Bhs + bnRow*BP + bnQ*8), Bh_g + off);
      cp16(smem_u32(Bls + bnRow*BP + bnQ*8), Bl_g + off);
    } else {
      int gn = n0 + bkNg*8;
      bool valid = gn < N;
      size_t off = (size_t)(k0+bkK)*ldb + gn;
      cp16p(smem_u32(Bhs + bkK*BP + bkNg*8), Bh_g + off, valid);
      cp16p(smem_u32(Bls + bkK*BP + bkNg*8), Bl_g + off, valid);
    }
  };

  // ldmatrix lane decodes
  const int lrow = lane & 7;
  const int lsel = (lane >> 3) & 1;
  const int lhi  = lane >> 4;

  // ---- prologue: stages 0,1 ----
  loadStage(0, 0); cp_commit();
  loadStage(1, 1); cp_commit();

  for (int c = 0; c < nch; c++){
    const int s = c % STAGES;
    cp_wait<1>();
    __syncthreads();               // the ONLY barrier per chunk

    // prefetch stage c+2 (writes stage (c-1)%3 — safe after the barrier)
    if (c+2 < nch) loadStage(c+2, (c+2) % STAGES);
    cp_commit();

    __nv_bfloat16* Ahs = sm + s*STAGE_EL;
    __nv_bfloat16* Als = Ahs + A_EL;
    __nv_bfloat16* Bhs = Als + A_EL;
    __nv_bfloat16* Bls = Bhs + B_EL;

    #pragma unroll
    for (int ks=0; ks<2; ks++){
      uint32_t ah[MF][4], al[MF][4];
      #pragma unroll
      for (int mf=0; mf<MF; mf++){
        int r = wm + mf*16 + lsel*8 + lrow;
        ldsm_x4(ah[mf], smem_u32(Ahs + r*AP + ks*16 + lhi*8));
        ldsm_x4(al[mf], smem_u32(Als + r*AP + ks*16 + lhi*8));
      }
      uint32_t bh[NF][2], bl[NF][2];
      #pragma unroll
      for (int nfp=0; nfp<NF/2; nfp++){
        int nb = wn + nfp*16;
        uint32_t rh[4], rl[4];
        if (TRANSB){
          int r = nb + lhi*8 + lrow;
          ldsm_x4(rh, smem_u32(Bhs + r*BP + ks*16 + lsel*8));
          ldsm_x4(rl, smem_u32(Bls + r*BP + ks*16 + lsel*8));
        } else {
          int r = ks*16 + lsel*8 + lrow;
          ldsm_x4_t(rh, smem_u32(Bhs + r*BP + nb + lhi*8));
          ldsm_x4_t(rl, smem_u32(Bls + r*BP + nb + lhi*8));
        }
        bh[2*nfp][0]=rh[0]; bh[2*nfp][1]=rh[1]; bh[2*nfp+1][0]=rh[2]; bh[2*nfp+1][1]=rh[3];
        bl[2*nfp][0]=rl[0]; bl[2*nfp][1]=rl[1]; bl[2*nfp+1][0]=rl[2]; bl[2*nfp+1][1]=rl[3];
      }
      // three independent passes: 8 independent MMAs between acc reuses
      #pragma unroll
      for (int mf=0; mf<MF; mf++)
        #pragma unroll
        for (int nf=0; nf<NF; nf++)
          mma_bf16(acc[mf][nf], ah[mf], bh[nf]);
      #pragma unroll
      for (int mf=0; mf<MF; mf++)
        #pragma unroll
        for (int nf=0; nf<NF; nf++)
          mma_bf16(acc[mf][nf], al[mf], bh[nf]);
      #pragma unroll
      for (int mf=0; mf<MF; mf++)
        #pragma unroll
        for (int nf=0; nf<NF; nf++)
          mma_bf16(acc[mf][nf], ah[mf], bl[nf]);
    }
  }

  float* Cfp = Cf + zo*sC1 + zi*sC2;
  __nv_bfloat16* Chp = Ch + zo*sC1 + zi*sC2;
  __nv_bfloat16* Clp = Cl + zo*sC1 + zi*sC2;

  // ---- epilogue ----
  #pragma unroll
  for (int mf=0; mf<MF; mf++){
    #pragma unroll
    for (int nf=0; nf<NF; nf++){
      int row = m0 + wm + mf*16 + grp;
      int col = n0 + wn + nf*8 + tig*2;
      if (col < N){
        float2 v0 = make_float2(acc[mf][nf][0], acc[mf][nf][1]);
        float2 v1 = make_float2(acc[mf][nf][2], acc[mf][nf][3]);
        if (bias){
          float2 bv = *reinterpret_cast<const float2*>(bias + col);
          v0.x += bv.x; v0.y += bv.y;
          v1.x += bv.x; v1.y += bv.y;
        }
        if (ACT == 1){
          v0.x = gelu_exact(v0.x); v0.y = gelu_exact(v0.y);
          v1.x = gelu_exact(v1.x); v1.y = gelu_exact(v1.y);
        }
        if (OUT == 0){
          *reinterpret_cast<float2*>(Cfp + (size_t)row*ldc + col)     = v0;
          *reinterpret_cast<float2*>(Cfp + (size_t)(row+8)*ldc + col) = v1;
        } else {
          uint32_t h0,l0,h1,l1;
          split_bf16_pair(v0.x, v0.y, h0, l0);
          split_bf16_pair(v1.x, v1.y, h1, l1);
          *reinterpret_cast<uint32_t*>(Chp + (size_t)row*ldc + col)     = h0;
          *reinterpret_cast<uint32_t*>(Clp + (size_t)row*ldc + col)     = l0;
          *reinterpret_cast<uint32_t*>(Chp + (size_t)(row+8)*ldc + col) = h1;
          *reinterpret_cast<uint32_t*>(Clp + (size_t)(row+8)*ldc + col) = l1;
        }
      }
    }
  }
}

// ---------------- weight split kernels ----------------------------------------
__global__ void split2_kernel(const float* __restrict__ src,
                              __nv_bfloat16* __restrict__ hi,
                              __nv_bfloat16* __restrict__ lo, size_t n2)
{
  for (size_t i = (size_t)blockIdx.x*blockDim.x + threadIdx.x;
       i < n2; i += (size_t)gridDim.x*blockDim.x){
    float2 v = reinterpret_cast<const float2*>(src)[i];
    uint32_t h,l; split_bf16_pair(v.x, v.y, h, l);
    reinterpret_cast<uint32_t*>(hi)[i] = h;
    reinterpret_cast<uint32_t*>(lo)[i] = l;
  }
}

__global__ void pack_qkv_split_kernel(const float* __restrict__ Wq,
                                      const float* __restrict__ Wk,
                                      const float* __restrict__ Wv,
                                      const float* __restrict__ bq,
                                      const float* __restrict__ bk,
                                      const float* __restrict__ bv)
{
  const size_t total = (size_t)LL*HH*QKVW;
  for (size_t idx = (size_t)blockIdx.x*blockDim.x + threadIdx.x;
       idx < total; idx += (size_t)gridDim.x*blockDim.x){
    int col = (int)(idx % QKVW);
    size_t rl = idx / QKVW;
    float v;
    if (col < HH)        v = Wq[rl*HH + col];
    else if (col < 2*HH) v = Wk[rl*HH + col - HH];
    else                 v = Wv[rl*HH + col - 2*HH];
    __nv_bfloat16 h,l; split_bf16_scalar(v, h, l);
    g_wqkvh[idx] = h; g_wqkvl[idx] = l;
  }
  for (size_t idx = (size_t)blockIdx.x*blockDim.x + threadIdx.x;
       idx < (size_t)LL*QKVW; idx += (size_t)gridDim.x*blockDim.x){
    int col = (int)(idx % QKVW);
    int l   = (int)(idx / QKVW);
    float v;
    if (col < HH)        v = bq[l*HH + col];
    else if (col < 2*HH) v = bk[l*HH + col - HH];
    else                 v = bv[l*HH + col - 2*HH];
    g_bqkv[idx] = v;
  }
}

// ---------------- embeddings + LN (writes fp32 + bf16 hi/lo) -----------------
__global__ void embed_ln_kernel(const int* __restrict__ ids,
                                const float* __restrict__ we,
                                const float* __restrict__ pe,
                                const float* __restrict__ te,
                                const float* __restrict__ g,
                                const float* __restrict__ b)
{
  int t = blockIdx.x;
  int s = t & (SS-1);
  int id = ids[t];
  const float* wrow = we + (size_t)id*HH;
  const float* prow = pe + (size_t)s*HH;
  float x[3];
  float lsum = 0.f;
  #pragma unroll
  for (int i=0;i<3;i++){
    int c = threadIdx.x + i*256;
    x[i] = wrow[c] + prow[c] + te[c];
    lsum += x[i];
  }
  float mean = blockSum<8>(lsum) * (1.0f/HH);
  float ls2 = 0.f;
  #pragma unroll
  for (int i=0;i<3;i++){ x[i] -= mean; ls2 += x[i]*x[i]; }
  float var = blockSum<8>(ls2) * (1.0f/HH);
  float inv = rsqrtf(var + 1e-12f);
  #pragma unroll
  for (int i=0;i<3;i++){
    int c = threadIdx.x + i*256;
    float v = x[i]*inv*g[c] + b[c];
    g_h[(size_t)t*HH + c] = v;
    __nv_bfloat16 h,l; split_bf16_scalar(v, h, l);
    g_hhi[(size_t)t*HH + c] = h;
    g_hlo[(size_t)t*HH + c] = l;
  }
}

// ---------------- residual + LN (in place on g_h; emits hi/lo too) -----------
__global__ void resln_kernel(const float* __restrict__ r,
                             const float* __restrict__ g,
                             const float* __restrict__ b)
{
  int t = blockIdx.x;
  float x[3];
  float lsum = 0.f;
  #pragma unroll
  for (int i=0;i<3;i++){
    int c = threadIdx.x + i*256;
    x[i] = g_h[(size_t)t*HH + c] + r[(size_t)t*HH + c];
    lsum += x[i];
  }
  float mean = blockSum<8>(lsum) * (1.0f/HH);
  float ls2 = 0.f;
  #pragma unroll
  for (int i=0;i<3;i++){ x[i] -= mean; ls2 += x[i]*x[i]; }
  float var = blockSum<8>(ls2) * (1.0f/HH);
  float inv = rsqrtf(var + 1e-12f);
  #pragma unroll
  for (int i=0;i<3;i++){
    int c = threadIdx.x + i*256;
    float v = x[i]*inv*g[c] + b[c];
    g_h[(size_t)t*HH + c] = v;
    __nv_bfloat16 h,l; split_bf16_scalar(v, h, l);
    g_hhi[(size_t)t*HH + c] = h;
    g_hlo[(size_t)t*HH + c] = l;
  }
}

// ---------------- masked softmax (fp32 in -> bf16 hi/lo out, truncated) ------
__global__ void softmax_kernel()
{
  int z = blockIdx.y;
  int s = blockIdx.x;
  const size_t base = ((size_t)z*SS + s)*SS;
  const float* row = g_scores + base;
  const int L = (s < PLEN) ? PLEN : (s + 1);
  const int E = (s/128 + 1) * 128;
  float x[4];
  float mx = -3.4e38f;
  #pragma unroll
  for (int i=0;i<4;i++){
    int j = threadIdx.x + i*128;
    x[i] = (j < L) ? row[j] * 0.125f : -3.4e38f;
    mx = fmaxf(mx, x[i]);
  }
  mx = blockMax<4>(mx);
  float ls = 0.f;
  #pragma unroll
  for (int i=0;i<4;i++){
    int j = threadIdx.x + i*128;
    x[i] = (j < L) ? __expf(x[i] - mx) : 0.f;
    ls += x[i];
  }
  float sum = blockSum<4>(ls);
  float inv = 1.0f / sum;
  #pragma unroll
  for (int i=0;i<4;i++){
    int j = threadIdx.x + i*128;
    if (j < L){
      float v = x[i] * inv;
      __nv_bfloat16 h,l; split_bf16_scalar(v, h, l);
      g_schi[base + j] = h;
      g_sclo[base + j] = l;
    } else if (j < E){
      g_schi[base + j] = __float2bfloat16(0.f);
      g_sclo[base + j] = __float2bfloat16(0.f);
    }
  }
}

// ---------------- cross entropy (single pass, online logsumexp) --------------
__global__ void zero_loss_kernel(){ g_loss_sum = 0.f; }

__global__ void ce_kernel(const int* __restrict__ labels)
{
  int r = blockIdx.x;
  int bb = r / NVALID_PER_B;
  int s  = PLEN + (r - bb*NVALID_PER_B);
  const float* row = g_logits + (size_t)r*VV;
  int lab = labels[bb*SS + s];

  // per-thread online (max, sum) in one pass
  float mx = -3.4e38f;
  float sm = 0.f;
  for (int j = threadIdx.x; j < VV; j += 256){
    float v = row[j];
    if (v > mx){
      sm = sm * __expf(mx - v) + 1.0f;
      mx = v;
    } else {
      sm += __expf(v - mx);
    }
  }
  float bM = blockMax<8>(mx);
  float contrib = (sm > 0.f) ? sm * __expf(mx - bM) : 0.f;
  float total = blockSum<8>(contrib);
  if (threadIdx.x == 0){
    float nll = (logf(total) + bM) - row[lab];
    atomicAdd(&g_loss_sum, nll);
  }
}

__global__ void finalize_kernel(float* out){
  out[0] = g_loss_sum * (1.0f/(float)NVALID);
}

// ---------------- host orchestration -----------------------------------------
template<int BN, bool TRANSB, int ACT, int OUT, int MASK>
static void launch_mm(const __nv_bfloat16* Ah, const __nv_bfloat16* Al,
                      const __nv_bfloat16* Bh, const __nv_bfloat16* Bl,
                      const float* bias,
                      float* Cf, __nv_bfloat16* Ch, __nv_bfloat16* Cl,
                      int M, int N, int K, int lda, int ldb, int ldc,
                      int batchInner,
                      long long sA1, long long sA2, long long sB1, long long sB2,
                      long long sC1, long long sC2, int gz)
{
  constexpr int AP = 40;
  constexpr int BROWS = TRANSB ? BN : 32;
  constexpr int BP = TRANSB ? 40 : (BN + 8);
  constexpr int STAGE_EL = 2*128*AP + 2*BROWS*BP;
  int smemsz = 3 * STAGE_EL * (int)sizeof(__nv_bfloat16);
  cudaFuncSetAttribute(gemm_mma<BN,TRANSB,ACT,OUT,MASK>,
                       cudaFuncAttributeMaxDynamicSharedMemorySize, smemsz);
  dim3 grid((N + BN - 1)/BN, M/128, gz);
  gemm_mma<BN,TRANSB,ACT,OUT,MASK><<<grid, 256, smemsz>>>(
      Ah, Al, Bh, Bl, bias, Cf, Ch, Cl, M, N, K, lda, ldb, ldc,
      batchInner, sA1, sA2, sB1, sB2, sC1, sC2);
}

extern "C" void kernel_launch(void* const* d_in, const int* in_sizes, int n_in,
                              void* d_out, int out_size)
{
  const int*   input_ids = (const int*)  d_in[0];
  const int*   labels    = (const int*)  d_in[1];
  const float* word_emb  = (const float*)d_in[2];
  const float* pos_emb   = (const float*)d_in[3];
  const float* type_emb  = (const float*)d_in[4];
  const float* eg        = (const float*)d_in[5];
  const float* eb        = (const float*)d_in[6];
  const float* Wq = (const float*)d_in[7];  const float* bq = (const float*)d_in[8];
  const float* Wk = (const float*)d_in[9];  const float* bk = (const float*)d_in[10];
  const float* Wv = (const float*)d_in[11]; const float* bv = (const float*)d_in[12];
  const float* Wo = (const float*)d_in[13]; const float* bo = (const float*)d_in[14];
  const float* ln1g = (const float*)d_in[15]; const float* ln1b = (const float*)d_in[16];
  const float* W1 = (const float*)d_in[17]; const float* bf1 = (const float*)d_in[18];
  const float* W2 = (const float*)d_in[19]; const float* bf2 = (const float*)d_in[20];
  const float* ln2g = (const float*)d_in[21]; const float* ln2b = (const float*)d_in[22];
  const float* Wc = (const float*)d_in[23]; const float* bc = (const float*)d_in[24];
  float* out = (float*)d_out;

  float *p_tmp, *p_sc, *p_lg, *p_bqkv;
  __nv_bfloat16 *p_hhi, *p_hlo, *p_qkvh, *p_qkvl, *p_ctxh, *p_ctxl;
  __nv_bfloat16 *p_ffnh, *p_ffnl, *p_schi, *p_sclo;
  __nv_bfloat16 *p_wqkvh, *p_wqkvl, *p_woh, *p_wol, *p_w1h, *p_w1l, *p_w2h, *p_w2l, *p_wch, *p_wcl;
  cudaGetSymbolAddress((void**)&p_tmp,  g_tmp);
  cudaGetSymbolAddress((void**)&p_sc,   g_scores);
  cudaGetSymbolAddress((void**)&p_lg,   g_logits);
  cudaGetSymbolAddress((void**)&p_bqkv, g_bqkv);
  cudaGetSymbolAddress((void**)&p_hhi,  g_hhi);
  cudaGetSymbolAddress((void**)&p_hlo,  g_hlo);
  cudaGetSymbolAddress((void**)&p_qkvh, g_qkvh);
  cudaGetSymbolAddress((void**)&p_qkvl, g_qkvl);
  cudaGetSymbolAddress((void**)&p_ctxh, g_ctxh);
  cudaGetSymbolAddress((void**)&p_ctxl, g_ctxl);
  cudaGetSymbolAddress((void**)&p_ffnh, g_ffnh);
  cudaGetSymbolAddress((void**)&p_ffnl, g_ffnl);
  cudaGetSymbolAddress((void**)&p_schi, g_schi);
  cudaGetSymbolAddress((void**)&p_sclo, g_sclo);
  cudaGetSymbolAddress((void**)&p_wqkvh, g_wqkvh);
  cudaGetSymbolAddress((void**)&p_wqkvl, g_wqkvl);
  cudaGetSymbolAddress((void**)&p_woh, g_woh);
  cudaGetSymbolAddress((void**)&p_wol, g_wol);
  cudaGetSymbolAddress((void**)&p_w1h, g_w1h);
  cudaGetSymbolAddress((void**)&p_w1l, g_w1l);
  cudaGetSymbolAddress((void**)&p_w2h, g_w2h);
  cudaGetSymbolAddress((void**)&p_w2l, g_w2l);
  cudaGetSymbolAddress((void**)&p_wch, g_wch);
  cudaGetSymbolAddress((void**)&p_wcl, g_wcl);

  zero_loss_kernel<<<1,1>>>();
  pack_qkv_split_kernel<<<1024,256>>>(Wq, Wk, Wv, bq, bk, bv);
  split2_kernel<<<1024,256>>>(Wo, p_woh, p_wol, (size_t)LL*HH*HH/2);
  split2_kernel<<<1024,256>>>(W1, p_w1h, p_w1l, (size_t)LL*HH*FFF/2);
  split2_kernel<<<1024,256>>>(W2, p_w2h, p_w2l, (size_t)LL*FFF*HH/2);
  split2_kernel<<<1024,256>>>(Wc, p_wch, p_wcl, (size_t)HH*VV/2);
  embed_ln_kernel<<<NTOK,256>>>(input_ids, word_emb, pos_emb, type_emb, eg, eb);

  const long long headStride = (long long)SS*HH;
  const long long qkvBatch   = (long long)SS*QKVW;
  const long long scStrideH  = (long long)SS*SS;
  const long long scStrideB  = (long long)NHH*SS*SS;

  for (int l = 0; l < LL; l++) {
    // fused QKV projection: [4096,768] @ [768,2304] + b -> bf16 hi/lo
    launch_mm<64,false,0,1,0>(p_hhi, p_hlo,
                              p_wqkvh + (size_t)l*HH*QKVW, p_wqkvl + (size_t)l*HH*QKVW,
                              p_bqkv + (size_t)l*QKVW,
                              nullptr, p_qkvh, p_qkvl,
                              NTOK, QKVW, HH, HH, QKVW, QKVW,
                              1, 0,0, 0,0, 0,0, 1);

    // scores = q @ k^T (NT), dead tiles skipped -> fp32
    launch_mm<64,true,0,0,1>(p_qkvh, p_qkvl, p_qkvh + HH, p_qkvl + HH,
                             nullptr, p_sc, nullptr, nullptr,
                             SS, SS, DHH, QKVW, QKVW, SS,
                             NHH,
                             qkvBatch, (long long)DHH,
                             qkvBatch, (long long)DHH,
                             scStrideB, scStrideH, BB*NHH);

    softmax_kernel<<<dim3(SS, BB*NHH), 128>>>();

    // ctx = attn @ v (NN), K truncated -> bf16 hi/lo
    launch_mm<64,false,0,1,2>(p_schi, p_sclo, p_qkvh + 2*HH, p_qkvl + 2*HH,
                              nullptr, nullptr, p_ctxh, p_ctxl,
                              SS, DHH, SS, SS, QKVW, HH,
                              NHH,
                              scStrideB, scStrideH,
                              qkvBatch, (long long)DHH,
                              headStride, (long long)DHH, BB*NHH);

    // output proj -> fp32 g_tmp, then residual LN
    launch_mm<64,false,0,0,0>(p_ctxh, p_ctxl,
                              p_woh + (size_t)l*HH*HH, p_wol + (size_t)l*HH*HH,
                              bo + (size_t)l*HH,
                              p_tmp, nullptr, nullptr,
                              NTOK, HH, HH, HH, HH, HH,
                              1, 0,0, 0,0, 0,0, 1);
    resln_kernel<<<NTOK,256>>>(p_tmp, ln1g + (size_t)l*HH, ln1b + (size_t)l*HH);

    // FFN1 (+GELU) -> bf16 hi/lo
    launch_mm<64,false,1,1,0>(p_hhi, p_hlo,
                              p_w1h + (size_t)l*HH*FFF, p_w1l + (size_t)l*HH*FFF,
                              bf1 + (size_t)l*FFF,
                              nullptr, p_ffnh, p_ffnl,
                              NTOK, FFF, HH, HH, FFF, FFF,
                              1, 0,0, 0,0, 0,0, 1);
    // FFN2 -> fp32 g_tmp, then residual LN
    launch_mm<64,false,0,0,0>(p_ffnh, p_ffnl,
                              p_w2h + (size_t)l*FFF*HH, p_w2l + (size_t)l*FFF*HH,
                              bf2 + (size_t)l*HH,
                              p_tmp, nullptr, nullptr,
                              NTOK, HH, FFF, FFF, HH, HH,
                              1, 0,0, 0,0, 0,0, 1);
    resln_kernel<<<NTOK,256>>>(p_tmp, ln2g + (size_t)l*HH, ln2b + (size_t)l*HH);
  }

  // logits for valid tokens only (rows s in [128,512) per batch, contiguous)
  launch_mm<64,false,0,0,0>(p_hhi + (size_t)PLEN*HH, p_hlo + (size_t)PLEN*HH,
                            p_wch, p_wcl, bc,
                            p_lg, nullptr, nullptr,
                            NVALID_PER_B, VV, HH, HH, VV, VV,
                            1,
                            (long long)SS*HH, 0,
                            0, 0,
                            (long long)NVALID_PER_B*VV, 0, BB);

  ce_kernel<<<NVALID,256>>>(labels);
  finalize_kernel<<<1,1>>>(out);
}

// round 16
// speedup vs baseline: 1.0230x; 1.0230x over previous
#include <cuda_runtime.h>
#include <cuda_bf16.h>
#include <cstdint>
#include <math.h>

// Problem constants
#define BB 8
#define SS 512
#define HH 768
#define NHH 12
#define DHH 64
#define LL 12
#define VV 21128
#define FFF 3072
#define PLEN 128
#define NTOK (BB*SS)
#define NVALID_PER_B (SS-PLEN)
#define NVALID (BB*NVALID_PER_B)
#define QKVW (3*HH)            // 2304

// ---------------- scratch (device globals; no allocations allowed) ----------
__device__ float g_h[NTOK*HH];                       // fp32 residual stream
__device__ __nv_bfloat16 g_hhi[NTOK*HH];
__device__ __nv_bfloat16 g_hlo[NTOK*HH];
__device__ __nv_bfloat16 g_qkvh[(size_t)NTOK*QKVW];
__device__ __nv_bfloat16 g_qkvl[(size_t)NTOK*QKVW];
__device__ __nv_bfloat16 g_ctxh[NTOK*HH];
__device__ __nv_bfloat16 g_ctxl[NTOK*HH];
__device__ float g_tmp[NTOK*HH];
__device__ __nv_bfloat16 g_ffnh[(size_t)NTOK*FFF];
__device__ __nv_bfloat16 g_ffnl[(size_t)NTOK*FFF];
__device__ float g_logits[(size_t)NVALID*VV];
// split weights
__device__ __nv_bfloat16 g_wqkvh[(size_t)LL*HH*QKVW];
__device__ __nv_bfloat16 g_wqkvl[(size_t)LL*HH*QKVW];
__device__ float g_bqkv[(size_t)LL*QKVW];
__device__ __nv_bfloat16 g_woh[(size_t)LL*HH*HH];
__device__ __nv_bfloat16 g_wol[(size_t)LL*HH*HH];
__device__ __nv_bfloat16 g_w1h[(size_t)LL*HH*FFF];
__device__ __nv_bfloat16 g_w1l[(size_t)LL*HH*FFF];
__device__ __nv_bfloat16 g_w2h[(size_t)LL*FFF*HH];
__device__ __nv_bfloat16 g_w2l[(size_t)LL*FFF*HH];
__device__ __nv_bfloat16 g_wch[(size_t)HH*VV];
__device__ __nv_bfloat16 g_wcl[(size_t)HH*VV];
__device__ float g_loss_sum;

// ---------------- helpers ----------------------------------------------------
__device__ __forceinline__ float warpSum(float v){
  #pragma unroll
  for (int o=16;o;o>>=1) v += __shfl_xor_sync(0xffffffffu, v, o);
  return v;
}
__device__ __forceinline__ float warpMax(float v){
  #pragma unroll
  for (int o=16;o;o>>=1) v = fmaxf(v, __shfl_xor_sync(0xffffffffu, v, o));
  return v;
}
template<int NW>
__device__ __forceinline__ float blockSum(float v){
  __shared__ float sh[NW];
  __syncthreads();
  v = warpSum(v);
  if ((threadIdx.x & 31)==0) sh[threadIdx.x>>5] = v;
  __syncthreads();
  float r = 0.f;
  #pragma unroll
  for (int i=0;i<NW;i++) r += sh[i];
  return r;
}
template<int NW>
__device__ __forceinline__ float blockMax(float v){
  __shared__ float sh[NW];
  __syncthreads();
  v = warpMax(v);
  if ((threadIdx.x & 31)==0) sh[threadIdx.x>>5] = v;
  __syncthreads();
  float r = -3.4e38f;
  #pragma unroll
  for (int i=0;i<NW;i++) r = fmaxf(r, sh[i]);
  return r;
}
__device__ __forceinline__ float gelu_exact(float x){
  return 0.5f * x * (1.0f + erff(x * 0.70710678118654752f));
}
__device__ __forceinline__ uint32_t smem_u32(const void* p){
  uint32_t a;
  asm("{ .reg .u64 t; cvta.to.shared.u64 t, %1; cvt.u32.u64 %0, t; }" : "=r"(a) : "l"(p));
  return a;
}
__device__ __forceinline__ void cp16(uint32_t dst, const void* src){
  asm volatile("cp.async.ca.shared.global [%0], [%1], 16;" :: "r"(dst), "l"(src));
}
__device__ __forceinline__ void cp16p(uint32_t dst, const void* src, bool valid){
  int sz = valid ? 16 : 0;
  asm volatile("cp.async.ca.shared.global [%0], [%1], 16, %2;"
               :: "r"(dst), "l"(src), "r"(sz));
}
__device__ __forceinline__ void cp_commit(){
  asm volatile("cp.async.commit_group;" ::: "memory");
}
template<int N>
__device__ __forceinline__ void cp_wait(){
  asm volatile("cp.async.wait_group %0;" :: "n"(N) : "memory");
}

// split a pair of fp32 into packed bf16 hi and lo (x0 -> low half)
__device__ __forceinline__ void split_bf16_pair(float x0, float x1,
                                                uint32_t& hi, uint32_t& lo){
  uint32_t h;
  asm("cvt.rn.bf16x2.f32 %0, %1, %2;" : "=r"(h) : "f"(x1), "f"(x0));
  float h0 = __uint_as_float(h << 16);
  float h1 = __uint_as_float(h & 0xffff0000u);
  float l0 = x0 - h0;
  float l1 = x1 - h1;
  asm("cvt.rn.bf16x2.f32 %0, %1, %2;" : "=r"(lo) : "f"(l1), "f"(l0));
  hi = h;
}
__device__ __forceinline__ void split_bf16_scalar(float x, __nv_bfloat16& h, __nv_bfloat16& l){
  h = __float2bfloat16(x);
  l = __float2bfloat16(x - __bfloat162float(h));
}

__device__ __forceinline__ void mma_bf16(float* d, const uint32_t* a, const uint32_t* b){
  asm volatile(
    "mma.sync.aligned.m16n8k16.row.col.f32.bf16.bf16.f32 "
    "{%0,%1,%2,%3}, {%4,%5,%6,%7}, {%8,%9}, {%0,%1,%2,%3};\n"
    : "+f"(d[0]), "+f"(d[1]), "+f"(d[2]), "+f"(d[3])
    : "r"(a[0]), "r"(a[1]), "r"(a[2]), "r"(a[3]), "r"(b[0]), "r"(b[1]));
}
__device__ __forceinline__ void ldsm_x4(uint32_t* r, uint32_t addr){
  asm volatile("ldmatrix.sync.aligned.m8n8.x4.shared.b16 {%0,%1,%2,%3}, [%4];"
    : "=r"(r[0]), "=r"(r[1]), "=r"(r[2]), "=r"(r[3]) : "r"(addr));
}
__device__ __forceinline__ void ldsm_x4_t(uint32_t* r, uint32_t addr){
  asm volatile("ldmatrix.sync.aligned.m8n8.x4.trans.shared.b16 {%0,%1,%2,%3}, [%4];"
    : "=r"(r[0]), "=r"(r[1]), "=r"(r[2]), "=r"(r[3]) : "r"(addr));
}

// ---------------- 3xBF16 GEMM, pre-split bf16, cp.async 3-stage, BK=32 -------
// C = A @ op(B) (+bias)(+GELU). A,B given as bf16 hi/lo pairs in gmem.
// TRANSB: B is [N,K] (NT). OUT: 0 -> fp32 C; 1 -> bf16 hi/lo C.
// BN=64, warp tile 32x32, ONE __syncthreads per 32-K chunk.
template<int BN, bool TRANSB, int ACT, int OUT>
__global__ __launch_bounds__(256,2) void gemm_mma(
    const __nv_bfloat16* __restrict__ Agh, const __nv_bfloat16* __restrict__ Agl,
    const __nv_bfloat16* __restrict__ Bgh, const __nv_bfloat16* __restrict__ Bgl,
    const float* __restrict__ bias,
    float* __restrict__ Cf, __nv_bfloat16* __restrict__ Ch, __nv_bfloat16* __restrict__ Cl,
    int M, int N, int K, int lda, int ldb, int ldc,
    int batchInner,
    long long sA1, long long sA2, long long sB1, long long sB2,
    long long sC1, long long sC2)
{
  constexpr int BM = 128;
  constexpr int BK = 32;
  constexpr int STAGES = 3;
  constexpr int WM = 32, WN = 32;
  constexpr int MF = 2, NF = 4;
  constexpr int WARPS_N = BN/32;         // 2

  constexpr int AP = 40;
  constexpr int BROWS = TRANSB ? BN : BK;
  constexpr int BP = TRANSB ? 40 : (BN + 8);
  constexpr int A_EL = BM*AP;
  constexpr int B_EL = BROWS*BP;
  constexpr int STAGE_EL = 2*A_EL + 2*B_EL;

  const int m0 = blockIdx.y * BM;
  const int n0 = blockIdx.x * BN;

  extern __shared__ __nv_bfloat16 sm[];

  const int tid  = threadIdx.x;
  const int wid  = tid >> 5;
  const int lane = tid & 31;
  const int grp  = lane >> 2;
  const int tig  = lane & 3;

  const int z  = blockIdx.z;
  const int zo = z / batchInner;
  const int zi = z - zo * batchInner;
  const __nv_bfloat16* Ah_g = Agh + zo*sA1 + zi*sA2;
  const __nv_bfloat16* Al_g = Agl + zo*sA1 + zi*sA2;
  const __nv_bfloat16* Bh_g = Bgh + zo*sB1 + zi*sB2;
  const __nv_bfloat16* Bl_g = Bgl + zo*sB1 + zi*sB2;

  const int wm = (wid / WARPS_N) * WM;
  const int wn = (wid % WARPS_N) * WN;

  float acc[MF][NF][4];
  #pragma unroll
  for (int i=0;i<MF;i++)
    #pragma unroll
    for (int j=0;j<NF;j++)
      #pragma unroll
      for (int r=0;r<4;r++) acc[i][j][r] = 0.f;

  const int nch = K / BK;

  const int aRow = tid >> 2;
  const int aQ   = tid & 3;
  const int bnRow = tid >> 2;
  const int bnQ   = tid & 3;
  const int bkK  = tid >> 3;
  const int bkNg = tid & 7;

  auto loadStage = [&](int c, int s){
    const int k0 = c * BK;
    __nv_bfloat16* Ahs = sm + s*STAGE_EL;
    __nv_bfloat16* Als = Ahs + A_EL;
    __nv_bfloat16* Bhs = Als + A_EL;
    __nv_bfloat16* Bls = Bhs + B_EL;
    #pragma unroll
    for (int i=0;i<2;i++){
      int row = aRow + i*64;
      size_t off = (size_t)(m0+row)*lda + k0 + aQ*8;
      cp16(smem_u32(Ahs + row*AP + aQ*8), Ah_g + off);
      cp16(smem_u32(Als + row*AP + aQ*8), Al_g + off);
    }
    if (TRANSB){
      size_t off = (size_t)(n0+bnRow)*ldb + k0 + bnQ*8;
      cp16(smem_u32(Bhs + bnRow*BP + bnQ*8), Bh_g + off);
      cp16(smem_u32(Bls + bnRow*BP + bnQ*8), Bl_g + off);
    } else {
      int gn = n0 + bkNg*8;
      bool valid = gn < N;
      size_t off = (size_t)(k0+bkK)*ldb + gn;
      cp16p(smem_u32(Bhs + bkK*BP + bkNg*8), Bh_g + off, valid);
      cp16p(smem_u32(Bls + bkK*BP + bkNg*8), Bl_g + off, valid);
    }
  };

  const int lrow = lane & 7;
  const int lsel = (lane >> 3) & 1;
  const int lhi  = lane >> 4;

  loadStage(0, 0); cp_commit();
  loadStage(1, 1); cp_commit();

  for (int c = 0; c < nch; c++){
    const int s = c % STAGES;
    cp_wait<1>();
    __syncthreads();

    if (c+2 < nch) loadStage(c+2, (c+2) % STAGES);
    cp_commit();

    __nv_bfloat16* Ahs = sm + s*STAGE_EL;
    __nv_bfloat16* Als = Ahs + A_EL;
    __nv_bfloat16* Bhs = Als + A_EL;
    __nv_bfloat16* Bls = Bhs + B_EL;

    #pragma unroll
    for (int ks=0; ks<2; ks++){
      uint32_t ah[MF][4], al[MF][4];
      #pragma unroll
      for (int mf=0; mf<MF; mf++){
        int r = wm + mf*16 + lsel*8 + lrow;
        ldsm_x4(ah[mf], smem_u32(Ahs + r*AP + ks*16 + lhi*8));
        ldsm_x4(al[mf], smem_u32(Als + r*AP + ks*16 + lhi*8));
      }
      uint32_t bh[NF][2], bl[NF][2];
      #pragma unroll
      for (int nfp=0; nfp<NF/2; nfp++){
        int nb = wn + nfp*16;
        uint32_t rh[4], rl[4];
        if (TRANSB){
          int r = nb + lhi*8 + lrow;
          ldsm_x4(rh, smem_u32(Bhs + r*BP + ks*16 + lsel*8));
          ldsm_x4(rl, smem_u32(Bls + r*BP + ks*16 + lsel*8));
        } else {
          int r = ks*16 + lsel*8 + lrow;
          ldsm_x4_t(rh, smem_u32(Bhs + r*BP + nb + lhi*8));
          ldsm_x4_t(rl, smem_u32(Bls + r*BP + nb + lhi*8));
        }
        bh[2*nfp][0]=rh[0]; bh[2*nfp][1]=rh[1]; bh[2*nfp+1][0]=rh[2]; bh[2*nfp+1][1]=rh[3];
        bl[2*nfp][0]=rl[0]; bl[2*nfp][1]=rl[1]; bl[2*nfp+1][0]=rl[2]; bl[2*nfp+1][1]=rl[3];
      }
      #pragma unroll
      for (int mf=0; mf<MF; mf++)
        #pragma unroll
        for (int nf=0; nf<NF; nf++)
          mma_bf16(acc[mf][nf], ah[mf], bh[nf]);
      #pragma unroll
      for (int mf=0; mf<MF; mf++)
        #pragma unroll
        for (int nf=0; nf<NF; nf++)
          mma_bf16(acc[mf][nf], al[mf], bh[nf]);
      #pragma unroll
      for (int mf=0; mf<MF; mf++)
        #pragma unroll
        for (int nf=0; nf<NF; nf++)
          mma_bf16(acc[mf][nf], ah[mf], bl[nf]);
    }
  }

  float* Cfp = Cf + zo*sC1 + zi*sC2;
  __nv_bfloat16* Chp = Ch + zo*sC1 + zi*sC2;
  __nv_bfloat16* Clp = Cl + zo*sC1 + zi*sC2;

  #pragma unroll
  for (int mf=0; mf<MF; mf++){
    #pragma unroll
    for (int nf=0; nf<NF; nf++){
      int row = m0 + wm + mf*16 + grp;
      int col = n0 + wn + nf*8 + tig*2;
      if (col < N){
        float2 v0 = make_float2(acc[mf][nf][0], acc[mf][nf][1]);
        float2 v1 = make_float2(acc[mf][nf][2], acc[mf][nf][3]);
        if (bias){
          float2 bv = *reinterpret_cast<const float2*>(bias + col);
          v0.x += bv.x; v0.y += bv.y;
          v1.x += bv.x; v1.y += bv.y;
        }
        if (ACT == 1){
          v0.x = gelu_exact(v0.x); v0.y = gelu_exact(v0.y);
          v1.x = gelu_exact(v1.x); v1.y = gelu_exact(v1.y);
        }
        if (OUT == 0){
          *reinterpret_cast<float2*>(Cfp + (size_t)row*ldc + col)     = v0;
          *reinterpret_cast<float2*>(Cfp + (size_t)(row+8)*ldc + col) = v1;
        } else {
          uint32_t h0,l0,h1,l1;
          split_bf16_pair(v0.x, v0.y, h0, l0);
          split_bf16_pair(v1.x, v1.y, h1, l1);
          *reinterpret_cast<uint32_t*>(Chp + (size_t)row*ldc + col)     = h0;
          *reinterpret_cast<uint32_t*>(Clp + (size_t)row*ldc + col)     = l0;
          *reinterpret_cast<uint32_t*>(Chp + (size_t)(row+8)*ldc + col) = h1;
          *reinterpret_cast<uint32_t*>(Clp + (size_t)(row+8)*ldc + col) = l1;
        }
      }
    }
  }
}

// ---------------- fused attention: scores + masked softmax + AV ---------------
// CTA: 32 queries (m-tile) x one (b,h). grid (16, 1, 96), 256 thr, 2 CTAs/SM.
// Phase 1: S(32 x J*64) in smem fp32 via 3xbf16 MMA, K streamed (64-key tiles).
// Phase 2: per-warp row softmax with prefix mask; P bf16 hi/lo overlaid on S.
// Phase 3: ctx = P @ V, V streamed; epilogue -> g_ctxh/g_ctxl.
#define AT_KP 72       // bf16 row stride for Q/K/V tiles (144B: aligned, conflict-free)
#define AT_SP 516      // fp32 row stride for S (2064B = 16 mod 128: conflict-free)

__global__ __launch_bounds__(256,2) void attn_kernel()
{
  extern __shared__ char asm_[];
  __nv_bfloat16* Qh = (__nv_bfloat16*)asm_;            // 32*72
  __nv_bfloat16* Ql = Qh + 32*AT_KP;                   // 32*72
  float* S = (float*)(Ql + 32*AT_KP);                  // 32*516 (offset 9216, 16B aligned)
  __nv_bfloat16* KV = (__nv_bfloat16*)(S + 32*AT_SP);  // 2 stages * 2*(64*72)

  constexpr int STG = 2*64*AT_KP;                      // els per stage (hi+lo)

  const int tid  = threadIdx.x;
  const int wid  = tid >> 5;
  const int lane = tid & 31;
  const int grp  = lane >> 2;
  const int tig  = lane & 3;
  const int lrow = lane & 7;
  const int lsel = (lane >> 3) & 1;
  const int lhi  = lane >> 4;

  const int z = blockIdx.z;
  const int b = z / NHH, h = z - b*NHH;
  const int m0 = blockIdx.x * 32;

  const int Keffq = (m0 + 32 > PLEN) ? (m0 + 32) : PLEN;
  const int J64 = (Keffq + 63) & ~63;
  const int J = J64 >> 6;

  const __nv_bfloat16* Qbh = g_qkvh + (size_t)(b*SS + m0)*QKVW + h*DHH;
  const __nv_bfloat16* Qbl = g_qkvl + (size_t)(b*SS + m0)*QKVW + h*DHH;
  const __nv_bfloat16* Kbh = g_qkvh + (size_t)b*SS*QKVW + HH + h*DHH;
  const __nv_bfloat16* Kbl = g_qkvl + (size_t)b*SS*QKVW + HH + h*DHH;
  const __nv_bfloat16* Vbh = Kbh + HH;
  const __nv_bfloat16* Vbl = Kbl + HH;

  // warp tile 16x16: wm in {0,16}, wn in {0,16,32,48}
  const int wm = (wid >> 2) * 16;
  const int wn = (wid & 3) * 16;

  // loaders
  auto loadQ = [&]{
    int r = tid >> 3, c = (tid & 7) * 8;
    cp16(smem_u32(Qh + r*AT_KP + c), Qbh + (size_t)r*QKVW + c);
    cp16(smem_u32(Ql + r*AT_KP + c), Qbl + (size_t)r*QKVW + c);
  };
  auto loadKV = [&](const __nv_bfloat16* Bh_, const __nv_bfloat16* Bl_, int t, int s){
    int row = tid >> 2;
    int c = (tid & 3) * 16;
    size_t go = (size_t)(t*64 + row)*QKVW;
    __nv_bfloat16* Th = KV + s*STG;
    __nv_bfloat16* Tl = Th + 64*AT_KP;
    cp16(smem_u32(Th + row*AT_KP + c    ), Bh_ + go + c);
    cp16(smem_u32(Th + row*AT_KP + c + 8), Bh_ + go + c + 8);
    cp16(smem_u32(Tl + row*AT_KP + c    ), Bl_ + go + c);
    cp16(smem_u32(Tl + row*AT_KP + c + 8), Bl_ + go + c + 8);
  };

  // ---- Phase 1: scores ----
  loadQ(); loadKV(Kbh, Kbl, 0, 0); cp_commit();

  for (int t = 0; t < J; t++){
    __syncthreads();                       // last readers of buf (t+1)&1 done
    if (t+1 < J){ loadKV(Kbh, Kbl, t+1, (t+1)&1); cp_commit(); cp_wait<1>(); }
    else        { cp_wait<0>(); }
    __syncthreads();                       // tile t (and Q) visible

    __nv_bfloat16* Kh = KV + (t&1)*STG;
    __nv_bfloat16* Kl = Kh + 64*AT_KP;

    float acc_s[2][4];
    #pragma unroll
    for (int nf=0; nf<2; nf++)
      #pragma unroll
      for (int r=0;r<4;r++) acc_s[nf][r] = 0.f;

    #pragma unroll
    for (int ks=0; ks<4; ks++){
      uint32_t ah[4], al[4];
      int r = wm + lsel*8 + lrow;
      ldsm_x4(ah, smem_u32(Qh + r*AT_KP + ks*16 + lhi*8));
      ldsm_x4(al, smem_u32(Ql + r*AT_KP + ks*16 + lhi*8));
      int rr = wn + lhi*8 + lrow;
      uint32_t rh[4], rl[4];
      ldsm_x4(rh, smem_u32(Kh + rr*AT_KP + ks*16 + lsel*8));
      ldsm_x4(rl, smem_u32(Kl + rr*AT_KP + ks*16 + lsel*8));
      mma_bf16(acc_s[0], ah, rh);
      mma_bf16(acc_s[1], ah, rh+2);
      mma_bf16(acc_s[0], al, rh);
      mma_bf16(acc_s[1], al, rh+2);
      mma_bf16(acc_s[0], ah, rl);
      mma_bf16(acc_s[1], ah, rl+2);
    }
    // write S block
    #pragma unroll
    for (int nf=0; nf<2; nf++){
      int col = t*64 + wn + nf*8 + 2*tig;
      *reinterpret_cast<float2*>(&S[(wm+grp)*AT_SP + col])   = make_float2(acc_s[nf][0], acc_s[nf][1]);
      *reinterpret_cast<float2*>(&S[(wm+grp+8)*AT_SP + col]) = make_float2(acc_s[nf][2], acc_s[nf][3]);
    }
  }

  __syncthreads();                          // S fully written; K buffers free
  loadKV(Vbh, Vbl, 0, 0); cp_commit();      // prefetch V0 during softmax

  // ---- Phase 2: softmax (warp-exclusive rows; P overlaid on S) ----
  {
    #pragma unroll
    for (int rr=0; rr<4; rr++){
      int r = wid*4 + rr;
      int sg = m0 + r;
      int L = (sg < PLEN) ? PLEN : (sg + 1);
      float x[16];
      float mx = -3.4e38f;
      #pragma unroll
      for (int i=0;i<16;i++){
        int j = lane + i*32;
        float v = (j < L) ? S[r*AT_SP + j] * 0.125f : -3.4e38f;
        x[i] = v;
        mx = fmaxf(mx, v);
      }
      mx = warpMax(mx);
      float sum = 0.f;
      #pragma unroll
      for (int i=0;i<16;i++){
        int j = lane + i*32;
        x[i] = (j < L) ? __expf(x[i] - mx) : 0.f;
        sum += x[i];
      }
      sum = warpSum(sum);                   // shfl reductions also order reads before writes
      float inv = 1.0f / sum;
      __nv_bfloat16* Ph = (__nv_bfloat16*)((char*)S + (size_t)r*AT_SP*4);
      __nv_bfloat16* Pl = (__nv_bfloat16*)((char*)S + (size_t)r*AT_SP*4 + 1040);
      #pragma unroll
      for (int i=0;i<16;i++){
        int j = lane + i*32;
        if (j < J64){
          float p = x[i] * inv;             // zero for j >= L
          __nv_bfloat16 hh, ll; split_bf16_scalar(p, hh, ll);
          Ph[j] = hh; Pl[j] = ll;
        }
      }
    }
  }

  // ---- Phase 3: ctx = P @ V ----
  float acc_c[2][4];
  #pragma unroll
  for (int nf=0; nf<2; nf++)
    #pragma unroll
    for (int r=0;r<4;r++) acc_c[nf][r] = 0.f;

  for (int t = 0; t < J; t++){
    __syncthreads();                        // P visible (t=0) / buf readers done
    if (t+1 < J){ loadKV(Vbh, Vbl, t+1, (t+1)&1); cp_commit(); cp_wait<1>(); }
    else        { cp_wait<0>(); }
    __syncthreads();

    __nv_bfloat16* Vh = KV + (t&1)*STG;
    __nv_bfloat16* Vl = Vh + 64*AT_KP;

    #pragma unroll
    for (int ks=0; ks<4; ks++){
      uint32_t ph[4], pl[4];
      int r = wm + lsel*8 + lrow;
      uint32_t pbase = smem_u32((char*)S + (size_t)r*AT_SP*4 + (t*64 + ks*16 + lhi*8)*2);
      ldsm_x4(ph, pbase);
      ldsm_x4(pl, pbase + 1040);
      int rv = ks*16 + lsel*8 + lrow;
      uint32_t vh[4], vl[4];
      ldsm_x4_t(vh, smem_u32(Vh + rv*AT_KP + wn + lhi*8));
      ldsm_x4_t(vl, smem_u32(Vl + rv*AT_KP + wn + lhi*8));
      mma_bf16(acc_c[0], ph, vh);
      mma_bf16(acc_c[1], ph, vh+2);
      mma_bf16(acc_c[0], pl, vh);
      mma_bf16(acc_c[1], pl, vh+2);
      mma_bf16(acc_c[0], ph, vl);
      mma_bf16(acc_c[1], ph, vl+2);
    }
  }

  // ---- epilogue: ctx -> bf16 hi/lo ----
  #pragma unroll
  for (int nf=0; nf<2; nf++){
    int row = m0 + wm + grp;
    int col = h*DHH + wn + nf*8 + 2*tig;
    size_t o0 = (size_t)(b*SS + row)*HH + col;
    size_t o1 = (size_t)(b*SS + row + 8)*HH + col;
    uint32_t h0,l0,h1,l1;
    split_bf16_pair(acc_c[nf][0], acc_c[nf][1], h0, l0);
    split_bf16_pair(acc_c[nf][2], acc_c[nf][3], h1, l1);
    *reinterpret_cast<uint32_t*>(g_ctxh + o0) = h0;
    *reinterpret_cast<uint32_t*>(g_ctxl + o0) = l0;
    *reinterpret_cast<uint32_t*>(g_ctxh + o1) = h1;
    *reinterpret_cast<uint32_t*>(g_ctxl + o1) = l1;
  }
}

// ---------------- weight split kernels ----------------------------------------
__global__ void split2_kernel(const float* __restrict__ src,
                              __nv_bfloat16* __restrict__ hi,
                              __nv_bfloat16* __restrict__ lo, size_t n2)
{
  for (size_t i = (size_t)blockIdx.x*blockDim.x + threadIdx.x;
       i < n2; i += (size_t)gridDim.x*blockDim.x){
    float2 v = reinterpret_cast<const float2*>(src)[i];
    uint32_t h,l; split_bf16_pair(v.x, v.y, h, l);
    reinterpret_cast<uint32_t*>(hi)[i] = h;
    reinterpret_cast<uint32_t*>(lo)[i] = l;
  }
}

__global__ void pack_qkv_split_kernel(const float* __restrict__ Wq,
                                      const float* __restrict__ Wk,
                                      const float* __restrict__ Wv,
                                      const float* __restrict__ bq,
                                      const float* __restrict__ bk,
                                      const float* __restrict__ bv)
{
  const size_t total = (size_t)LL*HH*QKVW;
  for (size_t idx = (size_t)blockIdx.x*blockDim.x + threadIdx.x;
       idx < total; idx += (size_t)gridDim.x*blockDim.x){
    int col = (int)(idx % QKVW);
    size_t rl = idx / QKVW;
    float v;
    if (col < HH)        v = Wq[rl*HH + col];
    else if (col < 2*HH) v = Wk[rl*HH + col - HH];
    else                 v = Wv[rl*HH + col - 2*HH];
    __nv_bfloat16 h,l; split_bf16_scalar(v, h, l);
    g_wqkvh[idx] = h; g_wqkvl[idx] = l;
  }
  for (size_t idx = (size_t)blockIdx.x*blockDim.x + threadIdx.x;
       idx < (size_t)LL*QKVW; idx += (size_t)gridDim.x*blockDim.x){
    int col = (int)(idx % QKVW);
    int l   = (int)(idx / QKVW);
    float v;
    if (col < HH)        v = bq[l*HH + col];
    else if (col < 2*HH) v = bk[l*HH + col - HH];
    else                 v = bv[l*HH + col - 2*HH];
    g_bqkv[idx] = v;
  }
}

// ---------------- embeddings + LN (writes fp32 + bf16 hi/lo) -----------------
__global__ void embed_ln_kernel(const int* __restrict__ ids,
                                const float* __restrict__ we,
                                const float* __restrict__ pe,
                                const float* __restrict__ te,
                                const float* __restrict__ g,
                                const float* __restrict__ b)
{
  int t = blockIdx.x;
  int s = t & (SS-1);
  int id = ids[t];
  const float* wrow = we + (size_t)id*HH;
  const float* prow = pe + (size_t)s*HH;
  float x[3];
  float lsum = 0.f;
  #pragma unroll
  for (int i=0;i<3;i++){
    int c = threadIdx.x + i*256;
    x[i] = wrow[c] + prow[c] + te[c];
    lsum += x[i];
  }
  float mean = blockSum<8>(lsum) * (1.0f/HH);
  float ls2 = 0.f;
  #pragma unroll
  for (int i=0;i<3;i++){ x[i] -= mean; ls2 += x[i]*x[i]; }
  float var = blockSum<8>(ls2) * (1.0f/HH);
  float inv = rsqrtf(var + 1e-12f);
  #pragma unroll
  for (int i=0;i<3;i++){
    int c = threadIdx.x + i*256;
    float v = x[i]*inv*g[c] + b[c];
    g_h[(size_t)t*HH + c] = v;
    __nv_bfloat16 h,l; split_bf16_scalar(v, h, l);
    g_hhi[(size_t)t*HH + c] = h;
    g_hlo[(size_t)t*HH + c] = l;
  }
}

// ---------------- residual + LN (in place on g_h; emits hi/lo too) -----------
__global__ void resln_kernel(const float* __restrict__ r,
                             const float* __restrict__ g,
                             const float* __restrict__ b)
{
  int t = blockIdx.x;
  float x[3];
  float lsum = 0.f;
  #pragma unroll
  for (int i=0;i<3;i++){
    int c = threadIdx.x + i*256;
    x[i] = g_h[(size_t)t*HH + c] + r[(size_t)t*HH + c];
    lsum += x[i];
  }
  float mean = blockSum<8>(lsum) * (1.0f/HH);
  float ls2 = 0.f;
  #pragma unroll
  for (int i=0;i<3;i++){ x[i] -= mean; ls2 += x[i]*x[i]; }
  float var = blockSum<8>(ls2) * (1.0f/HH);
  float inv = rsqrtf(var + 1e-12f);
  #pragma unroll
  for (int i=0;i<3;i++){
    int c = threadIdx.x + i*256;
    float v = x[i]*inv*g[c] + b[c];
    g_h[(size_t)t*HH + c] = v;
    __nv_bfloat16 h,l; split_bf16_scalar(v, h, l);
    g_hhi[(size_t)t*HH + c] = h;
    g_hlo[(size_t)t*HH + c] = l;
  }
}

// ---------------- cross entropy (single pass, online logsumexp) --------------
__global__ void zero_loss_kernel(){ g_loss_sum = 0.f; }

__global__ void ce_kernel(const int* __restrict__ labels)
{
  int r = blockIdx.x;
  int bb = r / NVALID_PER_B;
  int s  = PLEN + (r - bb*NVALID_PER_B);
  const float* row = g_logits + (size_t)r*VV;
  int lab = labels[bb*SS + s];

  float mx = -3.4e38f;
  float sm = 0.f;
  for (int j = threadIdx.x; j < VV; j += 256){
    float v = row[j];
    if (v > mx){
      sm = sm * __expf(mx - v) + 1.0f;
      mx = v;
    } else {
      sm += __expf(v - mx);
    }
  }
  float bM = blockMax<8>(mx);
  float contrib = (sm > 0.f) ? sm * __expf(mx - bM) : 0.f;
  float total = blockSum<8>(contrib);
  if (threadIdx.x == 0){
    float nll = (logf(total) + bM) - row[lab];
    atomicAdd(&g_loss_sum, nll);
  }
}

__global__ void finalize_kernel(float* out){
  out[0] = g_loss_sum * (1.0f/(float)NVALID);
}

// ---------------- host orchestration -----------------------------------------
template<int BN, bool TRANSB, int ACT, int OUT>
static void launch_mm(const __nv_bfloat16* Ah, const __nv_bfloat16* Al,
                      const __nv_bfloat16* Bh, const __nv_bfloat16* Bl,
                      const float* bias,
                      float* Cf, __nv_bfloat16* Ch, __nv_bfloat16* Cl,
                      int M, int N, int K, int lda, int ldb, int ldc,
                      int batchInner,
                      long long sA1, long long sA2, long long sB1, long long sB2,
                      long long sC1, long long sC2, int gz)
{
  constexpr int AP = 40;
  constexpr int BROWS = TRANSB ? BN : 32;
  constexpr int BP = TRANSB ? 40 : (BN + 8);
  constexpr int STAGE_EL = 2*128*AP + 2*BROWS*BP;
  int smemsz = 3 * STAGE_EL * (int)sizeof(__nv_bfloat16);
  cudaFuncSetAttribute(gemm_mma<BN,TRANSB,ACT,OUT>,
                       cudaFuncAttributeMaxDynamicSharedMemorySize, smemsz);
  dim3 grid((N + BN - 1)/BN, M/128, gz);
  gemm_mma<BN,TRANSB,ACT,OUT><<<grid, 256, smemsz>>>(
      Ah, Al, Bh, Bl, bias, Cf, Ch, Cl, M, N, K, lda, ldb, ldc,
      batchInner, sA1, sA2, sB1, sB2, sC1, sC2);
}

extern "C" void kernel_launch(void* const* d_in, const int* in_sizes, int n_in,
                              void* d_out, int out_size)
{
  const int*   input_ids = (const int*)  d_in[0];
  const int*   labels    = (const int*)  d_in[1];
  const float* word_emb  = (const float*)d_in[2];
  const float* pos_emb   = (const float*)d_in[3];
  const float* type_emb  = (const float*)d_in[4];
  const float* eg        = (const float*)d_in[5];
  const float* eb        = (const float*)d_in[6];
  const float* Wq = (const float*)d_in[7];  const float* bq = (const float*)d_in[8];
  const float* Wk = (const float*)d_in[9];  const float* bk = (const float*)d_in[10];
  const float* Wv = (const float*)d_in[11]; const float* bv = (const float*)d_in[12];
  const float* Wo = (const float*)d_in[13]; const float* bo = (const float*)d_in[14];
  const float* ln1g = (const float*)d_in[15]; const float* ln1b = (const float*)d_in[16];
  const float* W1 = (const float*)d_in[17]; const float* bf1 = (const float*)d_in[18];
  const float* W2 = (const float*)d_in[19]; const float* bf2 = (const float*)d_in[20];
  const float* ln2g = (const float*)d_in[21]; const float* ln2b = (const float*)d_in[22];
  const float* Wc = (const float*)d_in[23]; const float* bc = (const float*)d_in[24];
  float* out = (float*)d_out;

  float *p_tmp, *p_lg, *p_bqkv;
  __nv_bfloat16 *p_hhi, *p_hlo, *p_qkvh, *p_qkvl, *p_ctxh, *p_ctxl;
  __nv_bfloat16 *p_ffnh, *p_ffnl;
  __nv_bfloat16 *p_wqkvh, *p_wqkvl, *p_woh, *p_wol, *p_w1h, *p_w1l, *p_w2h, *p_w2l, *p_wch, *p_wcl;
  cudaGetSymbolAddress((void**)&p_tmp,  g_tmp);
  cudaGetSymbolAddress((void**)&p_lg,   g_logits);
  cudaGetSymbolAddress((void**)&p_bqkv, g_bqkv);
  cudaGetSymbolAddress((void**)&p_hhi,  g_hhi);
  cudaGetSymbolAddress((void**)&p_hlo,  g_hlo);
  cudaGetSymbolAddress((void**)&p_qkvh, g_qkvh);
  cudaGetSymbolAddress((void**)&p_qkvl, g_qkvl);
  cudaGetSymbolAddress((void**)&p_ctxh, g_ctxh);
  cudaGetSymbolAddress((void**)&p_ctxl, g_ctxl);
  cudaGetSymbolAddress((void**)&p_ffnh, g_ffnh);
  cudaGetSymbolAddress((void**)&p_ffnl, g_ffnl);
  cudaGetSymbolAddress((void**)&p_wqkvh, g_wqkvh);
  cudaGetSymbolAddress((void**)&p_wqkvl, g_wqkvl);
  cudaGetSymbolAddress((void**)&p_woh, g_woh);
  cudaGetSymbolAddress((void**)&p_wol, g_wol);
  cudaGetSymbolAddress((void**)&p_w1h, g_w1h);
  cudaGetSymbolAddress((void**)&p_w1l, g_w1l);
  cudaGetSymbolAddress((void**)&p_w2h, g_w2h);
  cudaGetSymbolAddress((void**)&p_w2l, g_w2l);
  cudaGetSymbolAddress((void**)&p_wch, g_wch);
  cudaGetSymbolAddress((void**)&p_wcl, g_wcl);

  zero_loss_kernel<<<1,1>>>();
  pack_qkv_split_kernel<<<1024,256>>>(Wq, Wk, Wv, bq, bk, bv);
  split2_kernel<<<1024,256>>>(Wo, p_woh, p_wol, (size_t)LL*HH*HH/2);
  split2_kernel<<<1024,256>>>(W1, p_w1h, p_w1l, (size_t)LL*HH*FFF/2);
  split2_kernel<<<1024,256>>>(W2, p_w2h, p_w2l, (size_t)LL*FFF*HH/2);
  split2_kernel<<<1024,256>>>(Wc, p_wch, p_wcl, (size_t)HH*VV/2);
  embed_ln_kernel<<<NTOK,256>>>(input_ids, word_emb, pos_emb, type_emb, eg, eb);

  // fused attention smem
  const int attn_smem = 2*32*AT_KP*2 + 32*AT_SP*4 + 2*2*64*AT_KP*2;   // 112128 B
  cudaFuncSetAttribute(attn_kernel, cudaFuncAttributeMaxDynamicSharedMemorySize, attn_smem);

  for (int l = 0; l < LL; l++) {
    // fused QKV projection: [4096,768] @ [768,2304] + b -> bf16 hi/lo
    launch_mm<64,false,0,1>(p_hhi, p_hlo,
                            p_wqkvh + (size_t)l*HH*QKVW, p_wqkvl + (size_t)l*HH*QKVW,
                            p_bqkv + (size_t)l*QKVW,
                            nullptr, p_qkvh, p_qkvl,
                            NTOK, QKVW, HH, HH, QKVW, QKVW,
                            1, 0,0, 0,0, 0,0, 1);

    // fused attention: scores + masked softmax + AV -> g_ctxh/g_ctxl
    attn_kernel<<<dim3(16,1,BB*NHH), 256, attn_smem>>>();

    // output proj -> fp32 g_tmp, then residual LN
    launch_mm<64,false,0,0>(p_ctxh, p_ctxl,
                            p_woh + (size_t)l*HH*HH, p_wol + (size_t)l*HH*HH,
                            bo + (size_t)l*HH,
                            p_tmp, nullptr, nullptr,
                            NTOK, HH, HH, HH, HH, HH,
                            1, 0,0, 0,0, 0,0, 1);
    resln_kernel<<<NTOK,256>>>(p_tmp, ln1g + (size_t)l*HH, ln1b + (size_t)l*HH);

    // FFN1 (+GELU) -> bf16 hi/lo
    launch_mm<64,false,1,1>(p_hhi, p_hlo,
                            p_w1h + (size_t)l*HH*FFF, p_w1l + (size_t)l*HH*FFF,
                            bf1 + (size_t)l*FFF,
                            nullptr, p_ffnh, p_ffnl,
                            NTOK, FFF, HH, HH, FFF, FFF,
                            1, 0,0, 0,0, 0,0, 1);
    // FFN2 -> fp32 g_tmp, then residual LN
    launch_mm<64,false,0,0>(p_ffnh, p_ffnl,
                            p_w2h + (size_t)l*FFF*HH, p_w2l + (size_t)l*FFF*HH,
                            bf2 + (size_t)l*HH,
                            p_tmp, nullptr, nullptr,
                            NTOK, HH, FFF, FFF, HH, HH,
                            1, 0,0, 0,0, 0,0, 1);
    resln_kernel<<<NTOK,256>>>(p_tmp, ln2g + (size_t)l*HH, ln2b + (size_t)l*HH);
  }

  // logits for valid tokens only (rows s in [128,512) per batch, contiguous)
  launch_mm<64,false,0,0>(p_hhi + (size_t)PLEN*HH, p_hlo + (size_t)PLEN*HH,
                          p_wch, p_wcl, bc,
                          p_lg, nullptr, nullptr,
                          NVALID_PER_B, VV, HH, HH, VV, VV,
                          1,
                          (long long)SS*HH, 0,
                          0, 0,
                          (long long)NVALID_PER_B*VV, 0, BB);

  ce_kernel<<<NVALID,256>>>(labels);
  finalize_kernel<<<1,1>>>(out);
}

// round 17
// speedup vs baseline: 1.0739x; 1.0498x over previous
#include <cuda_runtime.h>
#include <cuda_bf16.h>
#include <cstdint>
#include <math.h>

// Problem constants
#define BB 8
#define SS 512
#define HH 768
#define NHH 12
#define DHH 64
#define LL 12
#define VV 21128
#define FFF 3072
#define PLEN 128
#define NTOK (BB*SS)
#define NVALID_PER_B (SS-PLEN)
#define NVALID (BB*NVALID_PER_B)
#define QKVW (3*HH)            // 2304

// ---------------- scratch (device globals; no allocations allowed) ----------
__device__ float g_h[NTOK*HH];                       // fp32 residual stream
__device__ __nv_bfloat16 g_hhi[NTOK*HH];
__device__ __nv_bfloat16 g_hlo[NTOK*HH];
__device__ __nv_bfloat16 g_qkvh[(size_t)NTOK*QKVW];
__device__ __nv_bfloat16 g_qkvl[(size_t)NTOK*QKVW];
__device__ __nv_bfloat16 g_ctxh[NTOK*HH];
__device__ __nv_bfloat16 g_ctxl[NTOK*HH];
__device__ float g_tmp[NTOK*HH];
__device__ __nv_bfloat16 g_ffnh[(size_t)NTOK*FFF];
__device__ __nv_bfloat16 g_ffnl[(size_t)NTOK*FFF];
__device__ float g_logits[(size_t)NVALID*VV];
// split weights
__device__ __nv_bfloat16 g_wqkvh[(size_t)LL*HH*QKVW];
__device__ __nv_bfloat16 g_wqkvl[(size_t)LL*HH*QKVW];
__device__ float g_bqkv[(size_t)LL*QKVW];
__device__ __nv_bfloat16 g_woh[(size_t)LL*HH*HH];
__device__ __nv_bfloat16 g_wol[(size_t)LL*HH*HH];
__device__ __nv_bfloat16 g_w1h[(size_t)LL*HH*FFF];
__device__ __nv_bfloat16 g_w1l[(size_t)LL*HH*FFF];
__device__ __nv_bfloat16 g_w2h[(size_t)LL*FFF*HH];
__device__ __nv_bfloat16 g_w2l[(size_t)LL*FFF*HH];
__device__ __nv_bfloat16 g_wch[(size_t)HH*VV];
__device__ float g_loss_sum;

// ---------------- helpers ----------------------------------------------------
__device__ __forceinline__ float warpSum(float v){
  #pragma unroll
  for (int o=16;o;o>>=1) v += __shfl_xor_sync(0xffffffffu, v, o);
  return v;
}
__device__ __forceinline__ float warpMax(float v){
  #pragma unroll
  for (int o=16;o;o>>=1) v = fmaxf(v, __shfl_xor_sync(0xffffffffu, v, o));
  return v;
}
template<int NW>
__device__ __forceinline__ float blockSum(float v){
  __shared__ float sh[NW];
  __syncthreads();
  v = warpSum(v);
  if ((threadIdx.x & 31)==0) sh[threadIdx.x>>5] = v;
  __syncthreads();
  float r = 0.f;
  #pragma unroll
  for (int i=0;i<NW;i++) r += sh[i];
  return r;
}
template<int NW>
__device__ __forceinline__ float blockMax(float v){
  __shared__ float sh[NW];
  __syncthreads();
  v = warpMax(v);
  if ((threadIdx.x & 31)==0) sh[threadIdx.x>>5] = v;
  __syncthreads();
  float r = -3.4e38f;
  #pragma unroll
  for (int i=0;i<NW;i++) r = fmaxf(r, sh[i]);
  return r;
}
__device__ __forceinline__ float gelu_exact(float x){
  return 0.5f * x * (1.0f + erff(x * 0.70710678118654752f));
}
__device__ __forceinline__ uint32_t smem_u32(const void* p){
  uint32_t a;
  asm("{ .reg .u64 t; cvta.to.shared.u64 t, %1; cvt.u32.u64 %0, t; }" : "=r"(a) : "l"(p));
  return a;
}
__device__ __forceinline__ void cp16(uint32_t dst, const void* src){
  asm volatile("cp.async.ca.shared.global [%0], [%1], 16;" :: "r"(dst), "l"(src));
}
__device__ __forceinline__ void cp16p(uint32_t dst, const void* src, bool valid){
  int sz = valid ? 16 : 0;
  asm volatile("cp.async.ca.shared.global [%0], [%1], 16, %2;"
               :: "r"(dst), "l"(src), "r"(sz));
}
__device__ __forceinline__ void cp_commit(){
  asm volatile("cp.async.commit_group;" ::: "memory");
}
template<int N>
__device__ __forceinline__ void cp_wait(){
  asm volatile("cp.async.wait_group %0;" :: "n"(N) : "memory");
}

// split a pair of fp32 into packed bf16 hi and lo (x0 -> low half)
__device__ __forceinline__ void split_bf16_pair(float x0, float x1,
                                                uint32_t& hi, uint32_t& lo){
  uint32_t h;
  asm("cvt.rn.bf16x2.f32 %0, %1, %2;" : "=r"(h) : "f"(x1), "f"(x0));
  float h0 = __uint_as_float(h << 16);
  float h1 = __uint_as_float(h & 0xffff0000u);
  float l0 = x0 - h0;
  float l1 = x1 - h1;
  asm("cvt.rn.bf16x2.f32 %0, %1, %2;" : "=r"(lo) : "f"(l1), "f"(l0));
  hi = h;
}
__device__ __forceinline__ void split_bf16_scalar(float x, __nv_bfloat16& h, __nv_bfloat16& l){
  h = __float2bfloat16(x);
  l = __float2bfloat16(x - __bfloat162float(h));
}

__device__ __forceinline__ void mma_bf16(float* d, const uint32_t* a, const uint32_t* b){
  asm volatile(
    "mma.sync.aligned.m16n8k16.row.col.f32.bf16.bf16.f32 "
    "{%0,%1,%2,%3}, {%4,%5,%6,%7}, {%8,%9}, {%0,%1,%2,%3};\n"
    : "+f"(d[0]), "+f"(d[1]), "+f"(d[2]), "+f"(d[3])
    : "r"(a[0]), "r"(a[1]), "r"(a[2]), "r"(a[3]), "r"(b[0]), "r"(b[1]));
}
__device__ __forceinline__ void ldsm_x4(uint32_t* r, uint32_t addr){
  asm volatile("ldmatrix.sync.aligned.m8n8.x4.shared.b16 {%0,%1,%2,%3}, [%4];"
    : "=r"(r[0]), "=r"(r[1]), "=r"(r[2]), "=r"(r[3]) : "r"(addr));
}
__device__ __forceinline__ void ldsm_x4_t(uint32_t* r, uint32_t addr){
  asm volatile("ldmatrix.sync.aligned.m8n8.x4.trans.shared.b16 {%0,%1,%2,%3}, [%4];"
    : "=r"(r[0]), "=r"(r[1]), "=r"(r[2]), "=r"(r[3]) : "r"(addr));
}

// ---------------- 3x/1x BF16 GEMM, pre-split bf16, cp.async 3-stage, BK=32 ----
// C = A @ op(B) (+bias)(+GELU)(+res). A,B given as bf16 hi/lo pairs in gmem.
// TRANSB: B is [N,K] (NT). OUT: 0 -> fp32 C; 1 -> bf16 hi/lo C.
// TERMS: 3 -> hh+lh+hl (fp32-class); 1 -> hh only (bf16-class, logits path).
// res: optional fp32 residual added in OUT==0 epilogue (same ldc layout).
template<int BN, bool TRANSB, int ACT, int OUT, int TERMS>
__global__ __launch_bounds__(256,2) void gemm_mma(
    const __nv_bfloat16* __restrict__ Agh, const __nv_bfloat16* __restrict__ Agl,
    const __nv_bfloat16* __restrict__ Bgh, const __nv_bfloat16* __restrict__ Bgl,
    const float* __restrict__ bias, const float* __restrict__ res,
    float* __restrict__ Cf, __nv_bfloat16* __restrict__ Ch, __nv_bfloat16* __restrict__ Cl,
    int M, int N, int K, int lda, int ldb, int ldc,
    int batchInner,
    long long sA1, long long sA2, long long sB1, long long sB2,
    long long sC1, long long sC2)
{
  constexpr int BM = 128;
  constexpr int BK = 32;
  constexpr int STAGES = 3;
  constexpr int WM = 32, WN = 32;
  constexpr int MF = 2, NF = 4;
  constexpr int WARPS_N = BN/32;         // 2

  constexpr int AP = 40;
  constexpr int BROWS = TRANSB ? BN : BK;
  constexpr int BP = TRANSB ? 40 : (BN + 8);
  constexpr int A_EL = BM*AP;
  constexpr int B_EL = BROWS*BP;
  constexpr int STAGE_EL = 2*A_EL + 2*B_EL;

  const int m0 = blockIdx.y * BM;
  const int n0 = blockIdx.x * BN;

  extern __shared__ __nv_bfloat16 sm[];

  const int tid  = threadIdx.x;
  const int wid  = tid >> 5;
  const int lane = tid & 31;
  const int grp  = lane >> 2;
  const int tig  = lane & 3;

  const int z  = blockIdx.z;
  const int zo = z / batchInner;
  const int zi = z - zo * batchInner;
  const __nv_bfloat16* Ah_g = Agh + zo*sA1 + zi*sA2;
  const __nv_bfloat16* Al_g = Agl + zo*sA1 + zi*sA2;
  const __nv_bfloat16* Bh_g = Bgh + zo*sB1 + zi*sB2;
  const __nv_bfloat16* Bl_g = Bgl + zo*sB1 + zi*sB2;

  const int wm = (wid / WARPS_N) * WM;
  const int wn = (wid % WARPS_N) * WN;

  float acc[MF][NF][4];
  #pragma unroll
  for (int i=0;i<MF;i++)
    #pragma unroll
    for (int j=0;j<NF;j++)
      #pragma unroll
      for (int r=0;r<4;r++) acc[i][j][r] = 0.f;

  const int nch = K / BK;

  const int aRow = tid >> 2;
  const int aQ   = tid & 3;
  const int bnRow = tid >> 2;
  const int bnQ   = tid & 3;
  const int bkK  = tid >> 3;
  const int bkNg = tid & 7;

  auto loadStage = [&](int c, int s){
    const int k0 = c * BK;
    __nv_bfloat16* Ahs = sm + s*STAGE_EL;
    __nv_bfloat16* Als = Ahs + A_EL;
    __nv_bfloat16* Bhs = Als + A_EL;
    __nv_bfloat16* Bls = Bhs + B_EL;
    #pragma unroll
    for (int i=0;i<2;i++){
      int row = aRow + i*64;
      size_t off = (size_t)(m0+row)*lda + k0 + aQ*8;
      cp16(smem_u32(Ahs + row*AP + aQ*8), Ah_g + off);
      if (TERMS == 3) cp16(smem_u32(Als + row*AP + aQ*8), Al_g + off);
    }
    if (TRANSB){
      size_t off = (size_t)(n0+bnRow)*ldb + k0 + bnQ*8;
      cp16(smem_u32(Bhs + bnRow*BP + bnQ*8), Bh_g + off);
      if (TERMS == 3) cp16(smem_u32(Bls + bnRow*BP + bnQ*8), Bl_g + off);
    } else {
      int gn = n0 + bkNg*8;
      bool valid = gn < N;
      size_t off = (size_t)(k0+bkK)*ldb + gn;
      cp16p(smem_u32(Bhs + bkK*BP + bkNg*8), Bh_g + off, valid);
      if (TERMS == 3) cp16p(smem_u32(Bls + bkK*BP + bkNg*8), Bl_g + off, valid);
    }
  };

  const int lrow = lane & 7;
  const int lsel = (lane >> 3) & 1;
  const int lhi  = lane >> 4;

  loadStage(0, 0); cp_commit();
  loadStage(1, 1); cp_commit();

  for (int c = 0; c < nch; c++){
    const int s = c % STAGES;
    cp_wait<1>();
    __syncthreads();

    if (c+2 < nch) loadStage(c+2, (c+2) % STAGES);
    cp_commit();

    __nv_bfloat16* Ahs = sm + s*STAGE_EL;
    __nv_bfloat16* Als = Ahs + A_EL;
    __nv_bfloat16* Bhs = Als + A_EL;
    __nv_bfloat16* Bls = Bhs + B_EL;

    #pragma unroll
    for (int ks=0; ks<2; ks++){
      uint32_t ah[MF][4], al[MF][4];
      #pragma unroll
      for (int mf=0; mf<MF; mf++){
        int r = wm + mf*16 + lsel*8 + lrow;
        ldsm_x4(ah[mf], smem_u32(Ahs + r*AP + ks*16 + lhi*8));
        if (TERMS == 3) ldsm_x4(al[mf], smem_u32(Als + r*AP + ks*16 + lhi*8));
      }
      uint32_t bh[NF][2], bl[NF][2];
      #pragma unroll
      for (int nfp=0; nfp<NF/2; nfp++){
        int nb = wn + nfp*16;
        uint32_t rh[4], rl[4];
        if (TRANSB){
          int r = nb + lhi*8 + lrow;
          ldsm_x4(rh, smem_u32(Bhs + r*BP + ks*16 + lsel*8));
          if (TERMS == 3) ldsm_x4(rl, smem_u32(Bls + r*BP + ks*16 + lsel*8));
        } else {
          int r = ks*16 + lsel*8 + lrow;
          ldsm_x4_t(rh, smem_u32(Bhs + r*BP + nb + lhi*8));
          if (TERMS == 3) ldsm_x4_t(rl, smem_u32(Bls + r*BP + nb + lhi*8));
        }
        bh[2*nfp][0]=rh[0]; bh[2*nfp][1]=rh[1]; bh[2*nfp+1][0]=rh[2]; bh[2*nfp+1][1]=rh[3];
        if (TERMS == 3){
          bl[2*nfp][0]=rl[0]; bl[2*nfp][1]=rl[1]; bl[2*nfp+1][0]=rl[2]; bl[2*nfp+1][1]=rl[3];
        }
      }
      #pragma unroll
      for (int mf=0; mf<MF; mf++)
        #pragma unroll
        for (int nf=0; nf<NF; nf++)
          mma_bf16(acc[mf][nf], ah[mf], bh[nf]);
      if (TERMS == 3){
        #pragma unroll
        for (int mf=0; mf<MF; mf++)
          #pragma unroll
          for (int nf=0; nf<NF; nf++)
            mma_bf16(acc[mf][nf], al[mf], bh[nf]);
        #pragma unroll
        for (int mf=0; mf<MF; mf++)
          #pragma unroll
          for (int nf=0; nf<NF; nf++)
            mma_bf16(acc[mf][nf], ah[mf], bl[nf]);
      }
    }
  }

  float* Cfp = Cf + zo*sC1 + zi*sC2;
  __nv_bfloat16* Chp = Ch + zo*sC1 + zi*sC2;
  __nv_bfloat16* Clp = Cl + zo*sC1 + zi*sC2;
  const float* resp = res ? (res + zo*sC1 + zi*sC2) : nullptr;

  #pragma unroll
  for (int mf=0; mf<MF; mf++){
    #pragma unroll
    for (int nf=0; nf<NF; nf++){
      int row = m0 + wm + mf*16 + grp;
      int col = n0 + wn + nf*8 + tig*2;
      if (col < N){
        float2 v0 = make_float2(acc[mf][nf][0], acc[mf][nf][1]);
        float2 v1 = make_float2(acc[mf][nf][2], acc[mf][nf][3]);
        if (bias){
          float2 bv = *reinterpret_cast<const float2*>(bias + col);
          v0.x += bv.x; v0.y += bv.y;
          v1.x += bv.x; v1.y += bv.y;
        }
        if (ACT == 1){
          v0.x = gelu_exact(v0.x); v0.y = gelu_exact(v0.y);
          v1.x = gelu_exact(v1.x); v1.y = gelu_exact(v1.y);
        }
        if (OUT == 0){
          if (resp){
            float2 r0 = *reinterpret_cast<const float2*>(resp + (size_t)row*ldc + col);
            float2 r1 = *reinterpret_cast<const float2*>(resp + (size_t)(row+8)*ldc + col);
            v0.x += r0.x; v0.y += r0.y;
            v1.x += r1.x; v1.y += r1.y;
          }
          *reinterpret_cast<float2*>(Cfp + (size_t)row*ldc + col)     = v0;
          *reinterpret_cast<float2*>(Cfp + (size_t)(row+8)*ldc + col) = v1;
        } else {
          uint32_t h0,l0,h1,l1;
          split_bf16_pair(v0.x, v0.y, h0, l0);
          split_bf16_pair(v1.x, v1.y, h1, l1);
          *reinterpret_cast<uint32_t*>(Chp + (size_t)row*ldc + col)     = h0;
          *reinterpret_cast<uint32_t*>(Clp + (size_t)row*ldc + col)     = l0;
          *reinterpret_cast<uint32_t*>(Chp + (size_t)(row+8)*ldc + col) = h1;
          *reinterpret_cast<uint32_t*>(Clp + (size_t)(row+8)*ldc + col) = l1;
        }
      }
    }
  }
}

// ---------------- fused attention: scores + masked softmax + AV ---------------
#define AT_KP 72       // bf16 row stride for Q/K/V tiles
#define AT_SP 516      // fp32 row stride for S

__global__ __launch_bounds__(256,2) void attn_kernel()
{
  extern __shared__ char asm_[];
  __nv_bfloat16* Qh = (__nv_bfloat16*)asm_;
  __nv_bfloat16* Ql = Qh + 32*AT_KP;
  float* S = (float*)(Ql + 32*AT_KP);
  __nv_bfloat16* KV = (__nv_bfloat16*)(S + 32*AT_SP);

  constexpr int STG = 2*64*AT_KP;

  const int tid  = threadIdx.x;
  const int wid  = tid >> 5;
  const int lane = tid & 31;
  const int grp  = lane >> 2;
  const int tig  = lane & 3;
  const int lrow = lane & 7;
  const int lsel = (lane >> 3) & 1;
  const int lhi  = lane >> 4;

  const int z = blockIdx.z;
  const int b = z / NHH, h = z - b*NHH;
  const int m0 = blockIdx.x * 32;

  const int Keffq = (m0 + 32 > PLEN) ? (m0 + 32) : PLEN;
  const int J64 = (Keffq + 63) & ~63;
  const int J = J64 >> 6;

  const __nv_bfloat16* Qbh = g_qkvh + (size_t)(b*SS + m0)*QKVW + h*DHH;
  const __nv_bfloat16* Qbl = g_qkvl + (size_t)(b*SS + m0)*QKVW + h*DHH;
  const __nv_bfloat16* Kbh = g_qkvh + (size_t)b*SS*QKVW + HH + h*DHH;
  const __nv_bfloat16* Kbl = g_qkvl + (size_t)b*SS*QKVW + HH + h*DHH;
  const __nv_bfloat16* Vbh = Kbh + HH;
  const __nv_bfloat16* Vbl = Kbl + HH;

  const int wm = (wid >> 2) * 16;
  const int wn = (wid & 3) * 16;

  auto loadQ = [&]{
    int r = tid >> 3, c = (tid & 7) * 8;
    cp16(smem_u32(Qh + r*AT_KP + c), Qbh + (size_t)r*QKVW + c);
    cp16(smem_u32(Ql + r*AT_KP + c), Qbl + (size_t)r*QKVW + c);
  };
  auto loadKV = [&](const __nv_bfloat16* Bh_, const __nv_bfloat16* Bl_, int t, int s){
    int row = tid >> 2;
    int c = (tid & 3) * 16;
    size_t go = (size_t)(t*64 + row)*QKVW;
    __nv_bfloat16* Th = KV + s*STG;
    __nv_bfloat16* Tl = Th + 64*AT_KP;
    cp16(smem_u32(Th + row*AT_KP + c    ), Bh_ + go + c);
    cp16(smem_u32(Th + row*AT_KP + c + 8), Bh_ + go + c + 8);
    cp16(smem_u32(Tl + row*AT_KP + c    ), Bl_ + go + c);
    cp16(smem_u32(Tl + row*AT_KP + c + 8), Bl_ + go + c + 8);
  };

  // ---- Phase 1: scores ----
  loadQ(); loadKV(Kbh, Kbl, 0, 0); cp_commit();

  for (int t = 0; t < J; t++){
    __syncthreads();
    if (t+1 < J){ loadKV(Kbh, Kbl, t+1, (t+1)&1); cp_commit(); cp_wait<1>(); }
    else        { cp_wait<0>(); }
    __syncthreads();

    __nv_bfloat16* Kh = KV + (t&1)*STG;
    __nv_bfloat16* Kl = Kh + 64*AT_KP;

    float acc_s[2][4];
    #pragma unroll
    for (int nf=0; nf<2; nf++)
      #pragma unroll
      for (int r=0;r<4;r++) acc_s[nf][r] = 0.f;

    #pragma unroll
    for (int ks=0; ks<4; ks++){
      uint32_t ah[4], al[4];
      int r = wm + lsel*8 + lrow;
      ldsm_x4(ah, smem_u32(Qh + r*AT_KP + ks*16 + lhi*8));
      ldsm_x4(al, smem_u32(Ql + r*AT_KP + ks*16 + lhi*8));
      int rr = wn + lhi*8 + lrow;
      uint32_t rh[4], rl[4];
      ldsm_x4(rh, smem_u32(Kh + rr*AT_KP + ks*16 + lsel*8));
      ldsm_x4(rl, smem_u32(Kl + rr*AT_KP + ks*16 + lsel*8));
      mma_bf16(acc_s[0], ah, rh);
      mma_bf16(acc_s[1], ah, rh+2);
      mma_bf16(acc_s[0], al, rh);
      mma_bf16(acc_s[1], al, rh+2);
      mma_bf16(acc_s[0], ah, rl);
      mma_bf16(acc_s[1], ah, rl+2);
    }
    #pragma unroll
    for (int nf=0; nf<2; nf++){
      int col = t*64 + wn + nf*8 + 2*tig;
      *reinterpret_cast<float2*>(&S[(wm+grp)*AT_SP + col])   = make_float2(acc_s[nf][0], acc_s[nf][1]);
      *reinterpret_cast<float2*>(&S[(wm+grp+8)*AT_SP + col]) = make_float2(acc_s[nf][2], acc_s[nf][3]);
    }
  }

  __syncthreads();
  loadKV(Vbh, Vbl, 0, 0); cp_commit();

  // ---- Phase 2: softmax ----
  {
    #pragma unroll
    for (int rr=0; rr<4; rr++){
      int r = wid*4 + rr;
      int sg = m0 + r;
      int L = (sg < PLEN) ? PLEN : (sg + 1);
      float x[16];
      float mx = -3.4e38f;
      #pragma unroll
      for (int i=0;i<16;i++){
        int j = lane + i*32;
        float v = (j < L) ? S[r*AT_SP + j] * 0.125f : -3.4e38f;
        x[i] = v;
        mx = fmaxf(mx, v);
      }
      mx = warpMax(mx);
      float sum = 0.f;
      #pragma unroll
      for (int i=0;i<16;i++){
        int j = lane + i*32;
        x[i] = (j < L) ? __expf(x[i] - mx) : 0.f;
        sum += x[i];
      }
      sum = warpSum(sum);
      float inv = 1.0f / sum;
      __nv_bfloat16* Ph = (__nv_bfloat16*)((char*)S + (size_t)r*AT_SP*4);
      __nv_bfloat16* Pl = (__nv_bfloat16*)((char*)S + (size_t)r*AT_SP*4 + 1040);
      #pragma unroll
      for (int i=0;i<16;i++){
        int j = lane + i*32;
        if (j < J64){
          float p = x[i] * inv;
          __nv_bfloat16 hh, ll; split_bf16_scalar(p, hh, ll);
          Ph[j] = hh; Pl[j] = ll;
        }
      }
    }
  }

  // ---- Phase 3: ctx = P @ V ----
  float acc_c[2][4];
  #pragma unroll
  for (int nf=0; nf<2; nf++)
    #pragma unroll
    for (int r=0;r<4;r++) acc_c[nf][r] = 0.f;

  for (int t = 0; t < J; t++){
    __syncthreads();
    if (t+1 < J){ loadKV(Vbh, Vbl, t+1, (t+1)&1); cp_commit(); cp_wait<1>(); }
    else        { cp_wait<0>(); }
    __syncthreads();

    __nv_bfloat16* Vh = KV + (t&1)*STG;
    __nv_bfloat16* Vl = Vh + 64*AT_KP;

    #pragma unroll
    for (int ks=0; ks<4; ks++){
      uint32_t ph[4], pl[4];
      int r = wm + lsel*8 + lrow;
      uint32_t pbase = smem_u32((char*)S + (size_t)r*AT_SP*4 + (t*64 + ks*16 + lhi*8)*2);
      ldsm_x4(ph, pbase);
      ldsm_x4(pl, pbase + 1040);
      int rv = ks*16 + lsel*8 + lrow;
      uint32_t vh[4], vl[4];
      ldsm_x4_t(vh, smem_u32(Vh + rv*AT_KP + wn + lhi*8));
      ldsm_x4_t(vl, smem_u32(Vl + rv*AT_KP + wn + lhi*8));
      mma_bf16(acc_c[0], ph, vh);
      mma_bf16(acc_c[1], ph, vh+2);
      mma_bf16(acc_c[0], pl, vh);
      mma_bf16(acc_c[1], pl, vh+2);
      mma_bf16(acc_c[0], ph, vl);
      mma_bf16(acc_c[1], ph, vl+2);
    }
  }

  #pragma unroll
  for (int nf=0; nf<2; nf++){
    int row = m0 + wm + grp;
    int col = h*DHH + wn + nf*8 + 2*tig;
    size_t o0 = (size_t)(b*SS + row)*HH + col;
    size_t o1 = (size_t)(b*SS + row + 8)*HH + col;
    uint32_t h0,l0,h1,l1;
    split_bf16_pair(acc_c[nf][0], acc_c[nf][1], h0, l0);
    split_bf16_pair(acc_c[nf][2], acc_c[nf][3], h1, l1);
    *reinterpret_cast<uint32_t*>(g_ctxh + o0) = h0;
    *reinterpret_cast<uint32_t*>(g_ctxl + o0) = l0;
    *reinterpret_cast<uint32_t*>(g_ctxh + o1) = h1;
    *reinterpret_cast<uint32_t*>(g_ctxl + o1) = l1;
  }
}

// ---------------- weight split kernels ----------------------------------------
__global__ void split2_kernel(const float* __restrict__ src,
                              __nv_bfloat16* __restrict__ hi,
                              __nv_bfloat16* __restrict__ lo, size_t n2)
{
  for (size_t i = (size_t)blockIdx.x*blockDim.x + threadIdx.x;
       i < n2; i += (size_t)gridDim.x*blockDim.x){
    float2 v = reinterpret_cast<const float2*>(src)[i];
    uint32_t h,l; split_bf16_pair(v.x, v.y, h, l);
    reinterpret_cast<uint32_t*>(hi)[i] = h;
    reinterpret_cast<uint32_t*>(lo)[i] = l;
  }
}

// hi-only conversion (logits weights: lo never read)
__global__ void split1_kernel(const float* __restrict__ src,
                              __nv_bfloat16* __restrict__ hi, size_t n2)
{
  for (size_t i = (size_t)blockIdx.x*blockDim.x + threadIdx.x;
       i < n2; i += (size_t)gridDim.x*blockDim.x){
    float2 v = reinterpret_cast<const float2*>(src)[i];
    uint32_t h;
    asm("cvt.rn.bf16x2.f32 %0, %1, %2;" : "=r"(h) : "f"(v.y), "f"(v.x));
    reinterpret_cast<uint32_t*>(hi)[i] = h;
  }
}

__global__ void pack_qkv_split_kernel(const float* __restrict__ Wq,
                                      const float* __restrict__ Wk,
                                      const float* __restrict__ Wv,
                                      const float* __restrict__ bq,
                                      const float* __restrict__ bk,
                                      const float* __restrict__ bv)
{
  const size_t total = (size_t)LL*HH*QKVW;
  for (size_t idx = (size_t)blockIdx.x*blockDim.x + threadIdx.x;
       idx < total; idx += (size_t)gridDim.x*blockDim.x){
    int col = (int)(idx % QKVW);
    size_t rl = idx / QKVW;
    float v;
    if (col < HH)        v = Wq[rl*HH + col];
    else if (col < 2*HH) v = Wk[rl*HH + col - HH];
    else                 v = Wv[rl*HH + col - 2*HH];
    __nv_bfloat16 h,l; split_bf16_scalar(v, h, l);
    g_wqkvh[idx] = h; g_wqkvl[idx] = l;
  }
  for (size_t idx = (size_t)blockIdx.x*blockDim.x + threadIdx.x;
       idx < (size_t)LL*QKVW; idx += (size_t)gridDim.x*blockDim.x){
    int col = (int)(idx % QKVW);
    int l   = (int)(idx / QKVW);
    float v;
    if (col < HH)        v = bq[l*HH + col];
    else if (col < 2*HH) v = bk[l*HH + col - HH];
    else                 v = bv[l*HH + col - 2*HH];
    g_bqkv[idx] = v;
  }
}

// ---------------- embeddings + LN (writes fp32 + bf16 hi/lo) -----------------
__global__ void embed_ln_kernel(const int* __restrict__ ids,
                                const float* __restrict__ we,
                                const float* __restrict__ pe,
                                const float* __restrict__ te,
                                const float* __restrict__ g,
                                const float* __restrict__ b)
{
  int t = blockIdx.x;
  int s = t & (SS-1);
  int id = ids[t];
  const float* wrow = we + (size_t)id*HH;
  const float* prow = pe + (size_t)s*HH;
  float x[3];
  float lsum = 0.f;
  #pragma unroll
  for (int i=0;i<3;i++){
    int c = threadIdx.x + i*256;
    x[i] = wrow[c] + prow[c] + te[c];
    lsum += x[i];
  }
  float mean = blockSum<8>(lsum) * (1.0f/HH);
  float ls2 = 0.f;
  #pragma unroll
  for (int i=0;i<3;i++){ x[i] -= mean; ls2 += x[i]*x[i]; }
  float var = blockSum<8>(ls2) * (1.0f/HH);
  float inv = rsqrtf(var + 1e-12f);
  #pragma unroll
  for (int i=0;i<3;i++){
    int c = threadIdx.x + i*256;
    float v = x[i]*inv*g[c] + b[c];
    g_h[(size_t)t*HH + c] = v;
    __nv_bfloat16 h,l; split_bf16_scalar(v, h, l);
    g_hhi[(size_t)t*HH + c] = h;
    g_hlo[(size_t)t*HH + c] = l;
  }
}

// ---------------- LN only (input already has residual added) -----------------
__global__ void ln_only_kernel(const float* __restrict__ xin,
                               const float* __restrict__ g,
                               const float* __restrict__ b)
{
  int t = blockIdx.x;
  float x[3];
  float lsum = 0.f;
  #pragma unroll
  for (int i=0;i<3;i++){
    int c = threadIdx.x + i*256;
    x[i] = xin[(size_t)t*HH + c];
    lsum += x[i];
  }
  float mean = blockSum<8>(lsum) * (1.0f/HH);
  float ls2 = 0.f;
  #pragma unroll
  for (int i=0;i<3;i++){ x[i] -= mean; ls2 += x[i]*x[i]; }
  float var = blockSum<8>(ls2) * (1.0f/HH);
  float inv = rsqrtf(var + 1e-12f);
  #pragma unroll
  for (int i=0;i<3;i++){
    int c = threadIdx.x + i*256;
    float v = x[i]*inv*g[c] + b[c];
    g_h[(size_t)t*HH + c] = v;
    __nv_bfloat16 h,l; split_bf16_scalar(v, h, l);
    g_hhi[(size_t)t*HH + c] = h;
    g_hlo[(size_t)t*HH + c] = l;
  }
}

// ---------------- cross entropy (single pass, online logsumexp) --------------
__global__ void zero_loss_kernel(){ g_loss_sum = 0.f; }

__global__ void ce_kernel(const int* __restrict__ labels)
{
  int r = blockIdx.x;
  int bb = r / NVALID_PER_B;
  int s  = PLEN + (r - bb*NVALID_PER_B);
  const float* row = g_logits + (size_t)r*VV;
  int lab = labels[bb*SS + s];

  float mx = -3.4e38f;
  float sm = 0.f;
  for (int j = threadIdx.x; j < VV; j += 256){
    float v = row[j];
    if (v > mx){
      sm = sm * __expf(mx - v) + 1.0f;
      mx = v;
    } else {
      sm += __expf(v - mx);
    }
  }
  float bM = blockMax<8>(mx);
  float contrib = (sm > 0.f) ? sm * __expf(mx - bM) : 0.f;
  float total = blockSum<8>(contrib);
  if (threadIdx.x == 0){
    float nll = (logf(total) + bM) - row[lab];
    atomicAdd(&g_loss_sum, nll);
  }
}

__global__ void finalize_kernel(float* out){
  out[0] = g_loss_sum * (1.0f/(float)NVALID);
}

// ---------------- host orchestration -----------------------------------------
template<int BN, bool TRANSB, int ACT, int OUT, int TERMS>
static void launch_mm(const __nv_bfloat16* Ah, const __nv_bfloat16* Al,
                      const __nv_bfloat16* Bh, const __nv_bfloat16* Bl,
                      const float* bias, const float* res,
                      float* Cf, __nv_bfloat16* Ch, __nv_bfloat16* Cl,
                      int M, int N, int K, int lda, int ldb, int ldc,
                      int batchInner,
                      long long sA1, long long sA2, long long sB1, long long sB2,
                      long long sC1, long long sC2, int gz)
{
  constexpr int AP = 40;
  constexpr int BROWS = TRANSB ? BN : 32;
  constexpr int BP = TRANSB ? 40 : (BN + 8);
  constexpr int STAGE_EL = 2*128*AP + 2*BROWS*BP;
  int smemsz = 3 * STAGE_EL * (int)sizeof(__nv_bfloat16);
  cudaFuncSetAttribute(gemm_mma<BN,TRANSB,ACT,OUT,TERMS>,
                       cudaFuncAttributeMaxDynamicSharedMemorySize, smemsz);
  dim3 grid((N + BN - 1)/BN, M/128, gz);
  gemm_mma<BN,TRANSB,ACT,OUT,TERMS><<<grid, 256, smemsz>>>(
      Ah, Al, Bh, Bl, bias, res, Cf, Ch, Cl, M, N, K, lda, ldb, ldc,
      batchInner, sA1, sA2, sB1, sB2, sC1, sC2);
}

extern "C" void kernel_launch(void* const* d_in, const int* in_sizes, int n_in,
                              void* d_out, int out_size)
{
  const int*   input_ids = (const int*)  d_in[0];
  const int*   labels    = (const int*)  d_in[1];
  const float* word_emb  = (const float*)d_in[2];
  const float* pos_emb   = (const float*)d_in[3];
  const float* type_emb  = (const float*)d_in[4];
  const float* eg        = (const float*)d_in[5];
  const float* eb        = (const float*)d_in[6];
  const float* Wq = (const float*)d_in[7];  const float* bq = (const float*)d_in[8];
  const float* Wk = (const float*)d_in[9];  const float* bk = (const float*)d_in[10];
  const float* Wv = (const float*)d_in[11]; const float* bv = (const float*)d_in[12];
  const float* Wo = (const float*)d_in[13]; const float* bo = (const float*)d_in[14];
  const float* ln1g = (const float*)d_in[15]; const float* ln1b = (const float*)d_in[16];
  const float* W1 = (const float*)d_in[17]; const float* bf1 = (const float*)d_in[18];
  const float* W2 = (const float*)d_in[19]; const float* bf2 = (const float*)d_in[20];
  const float* ln2g = (const float*)d_in[21]; const float* ln2b = (const float*)d_in[22];
  const float* Wc = (const float*)d_in[23]; const float* bc = (const float*)d_in[24];
  float* out = (float*)d_out;

  float *p_h, *p_tmp, *p_lg, *p_bqkv;
  __nv_bfloat16 *p_hhi, *p_hlo, *p_qkvh, *p_qkvl, *p_ctxh, *p_ctxl;
  __nv_bfloat16 *p_ffnh, *p_ffnl;
  __nv_bfloat16 *p_wqkvh, *p_wqkvl, *p_woh, *p_wol, *p_w1h, *p_w1l, *p_w2h, *p_w2l, *p_wch;
  cudaGetSymbolAddress((void**)&p_h,    g_h);
  cudaGetSymbolAddress((void**)&p_tmp,  g_tmp);
  cudaGetSymbolAddress((void**)&p_lg,   g_logits);
  cudaGetSymbolAddress((void**)&p_bqkv, g_bqkv);
  cudaGetSymbolAddress((void**)&p_hhi,  g_hhi);
  cudaGetSymbolAddress((void**)&p_hlo,  g_hlo);
  cudaGetSymbolAddress((void**)&p_qkvh, g_qkvh);
  cudaGetSymbolAddress((void**)&p_qkvl, g_qkvl);
  cudaGetSymbolAddress((void**)&p_ctxh, g_ctxh);
  cudaGetSymbolAddress((void**)&p_ctxl, g_ctxl);
  cudaGetSymbolAddress((void**)&p_ffnh, g_ffnh);
  cudaGetSymbolAddress((void**)&p_ffnl, g_ffnl);
  cudaGetSymbolAddress((void**)&p_wqkvh, g_wqkvh);
  cudaGetSymbolAddress((void**)&p_wqkvl, g_wqkvl);
  cudaGetSymbolAddress((void**)&p_woh, g_woh);
  cudaGetSymbolAddress((void**)&p_wol, g_wol);
  cudaGetSymbolAddress((void**)&p_w1h, g_w1h);
  cudaGetSymbolAddress((void**)&p_w1l, g_w1l);
  cudaGetSymbolAddress((void**)&p_w2h, g_w2h);
  cudaGetSymbolAddress((void**)&p_w2l, g_w2l);
  cudaGetSymbolAddress((void**)&p_wch, g_wch);

  zero_loss_kernel<<<1,1>>>();
  pack_qkv_split_kernel<<<1024,256>>>(Wq, Wk, Wv, bq, bk, bv);
  split2_kernel<<<1024,256>>>(Wo, p_woh, p_wol, (size_t)LL*HH*HH/2);
  split2_kernel<<<1024,256>>>(W1, p_w1h, p_w1l, (size_t)LL*HH*FFF/2);
  split2_kernel<<<1024,256>>>(W2, p_w2h, p_w2l, (size_t)LL*FFF*HH/2);
  split1_kernel<<<1024,256>>>(Wc, p_wch, (size_t)HH*VV/2);
  embed_ln_kernel<<<NTOK,256>>>(input_ids, word_emb, pos_emb, type_emb, eg, eb);

  const int attn_smem = 2*32*AT_KP*2 + 32*AT_SP*4 + 2*2*64*AT_KP*2;
  cudaFuncSetAttribute(attn_kernel, cudaFuncAttributeMaxDynamicSharedMemorySize, attn_smem);

  for (int l = 0; l < LL; l++) {
    // fused QKV projection: [4096,768] @ [768,2304] + b -> bf16 hi/lo
    launch_mm<64,false,0,1,3>(p_hhi, p_hlo,
                              p_wqkvh + (size_t)l*HH*QKVW, p_wqkvl + (size_t)l*HH*QKVW,
                              p_bqkv + (size_t)l*QKVW, nullptr,
                              nullptr, p_qkvh, p_qkvl,
                              NTOK, QKVW, HH, HH, QKVW, QKVW,
                              1, 0,0, 0,0, 0,0, 1);

    // fused attention: scores + masked softmax + AV -> g_ctxh/g_ctxl
    attn_kernel<<<dim3(16,1,BB*NHH), 256, attn_smem>>>();

    // output proj + residual -> fp32 g_tmp, then LN
    launch_mm<64,false,0,0,3>(p_ctxh, p_ctxl,
                              p_woh + (size_t)l*HH*HH, p_wol + (size_t)l*HH*HH,
                              bo + (size_t)l*HH, p_h,
                              p_tmp, nullptr, nullptr,
                              NTOK, HH, HH, HH, HH, HH,
                              1, 0,0, 0,0, 0,0, 1);
    ln_only_kernel<<<NTOK,256>>>(p_tmp, ln1g + (size_t)l*HH, ln1b + (size_t)l*HH);

    // FFN1 (+GELU) -> bf16 hi/lo
    launch_mm<64,false,1,1,3>(p_hhi, p_hlo,
                              p_w1h + (size_t)l*HH*FFF, p_w1l + (size_t)l*HH*FFF,
                              bf1 + (size_t)l*FFF, nullptr,
                              nullptr, p_ffnh, p_ffnl,
                              NTOK, FFF, HH, HH, FFF, FFF,
                              1, 0,0, 0,0, 0,0, 1);
    // FFN2 + residual -> fp32 g_tmp, then LN
    launch_mm<64,false,0,0,3>(p_ffnh, p_ffnl,
                              p_w2h + (size_t)l*FFF*HH, p_w2l + (size_t)l*FFF*HH,
                              bf2 + (size_t)l*HH, p_h,
                              p_tmp, nullptr, nullptr,
                              NTOK, HH, FFF, FFF, HH, HH,
                              1, 0,0, 0,0, 0,0, 1);
    ln_only_kernel<<<NTOK,256>>>(p_tmp, ln2g + (size_t)l*HH, ln2b + (size_t)l*HH);
  }

  // logits: bf16 1-term (error averages out in CE over 3072 tokens)
  launch_mm<64,false,0,0,1>(p_hhi + (size_t)PLEN*HH, p_hlo + (size_t)PLEN*HH,
                            p_wch, p_wch, bc, nullptr,
                            p_lg, nullptr, nullptr,
                            NVALID_PER_B, VV, HH, HH, VV, VV,
                            1,
                            (long long)SS*HH, 0,
                            0, 0,
                            (long long)NVALID_PER_B*VV, 0, BB);

  ce_kernel<<<NVALID,256>>>(labels);
  finalize_kernel<<<1,1>>>(out);
}